// round 1
// baseline (speedup 1.0000x reference)
#include <cuda_runtime.h>
#include <math.h>

// ---------------------------------------------------------------------------
// TransformerBlock: B=2, L=2048, D=2048, H=16, DH=128, DFF=8192  (all fp32)
// Round 0: correct fp32 baseline. SGEMM-NT tiled kernels + flash-style causal
// attention. Scratch in __device__ globals (no allocations).
// ---------------------------------------------------------------------------

#define KB   2
#define KL   2048
#define KD   2048
#define KH   16
#define KDH  128
#define KDFF 8192
#define KM   (KB * KL)   // 4096 rows

// Scratch (device globals; ~300 MB total)
__device__ float g_h[(size_t)KM * KD];
__device__ float g_q[(size_t)KM * KD];
__device__ float g_k[(size_t)KM * KD];
__device__ float g_v[(size_t)KM * KD];
__device__ float g_o[(size_t)KM * KD];
__device__ float g_u[(size_t)KM * KDFF];

// ---------------------------------------------------------------------------
// RMSNorm: one block per row of D=2048
// ---------------------------------------------------------------------------
__global__ __launch_bounds__(256) void rmsnorm_kernel(
    const float* __restrict__ x, const float* __restrict__ w,
    float* __restrict__ y)
{
    int row = blockIdx.x;
    const float* xr = x + (size_t)row * KD;
    float*       yr = y + (size_t)row * KD;

    float s = 0.f;
    #pragma unroll
    for (int i = threadIdx.x; i < KD; i += 256) {
        float v = xr[i];
        s += v * v;
    }
    __shared__ float red[256];
    red[threadIdx.x] = s;
    __syncthreads();
    #pragma unroll
    for (int st = 128; st > 0; st >>= 1) {
        if (threadIdx.x < st) red[threadIdx.x] += red[threadIdx.x + st];
        __syncthreads();
    }
    float inv = rsqrtf(red[0] * (1.0f / KD) + 1e-8f);
    #pragma unroll
    for (int i = threadIdx.x; i < KD; i += 256)
        yr[i] = xr[i] * inv * w[i];
}

// ---------------------------------------------------------------------------
// SGEMM NT:  C[M,N] = A[M,K] @ Bw[N,K]^T   (both K-contiguous)
// 128x128 block tile, BK=8, 256 threads, 8x8 per thread.
// EPI: 0 = none, 1 = exact-erf GELU, 2 = residual add (C = R + acc)
// Requires M%128==0, N%128==0, K%8==0 (true for all calls here).
// ---------------------------------------------------------------------------
#define GBM 128
#define GBN 128
#define GBK 8

template<int EPI>
__global__ __launch_bounds__(256) void gemm_nt_kernel(
    const float* __restrict__ A, const float* __restrict__ Bw,
    float* __restrict__ C, const float* __restrict__ R,
    int M, int N, int K)
{
    __shared__ float As[GBK][GBM];
    __shared__ float Bs[GBK][GBN];

    const int tid = threadIdx.x;
    const int bm  = blockIdx.y * GBM;
    const int bn  = blockIdx.x * GBN;
    const int tx  = tid & 15;   // 0..15
    const int ty  = tid >> 4;   // 0..15

    // load mapping: each thread loads one float4 of A and one of B per k-tile
    const int arow = tid >> 1;           // 0..127
    const int acol = (tid & 1) * 4;      // 0 or 4

    const float* Aptr = A  + (size_t)(bm + arow) * K + acol;
    const float* Bptr = Bw + (size_t)(bn + arow) * K + acol;

    float acc[8][8];
    #pragma unroll
    for (int i = 0; i < 8; i++)
        #pragma unroll
        for (int j = 0; j < 8; j++) acc[i][j] = 0.f;

    for (int k0 = 0; k0 < K; k0 += GBK) {
        float4 av = *(const float4*)(Aptr + k0);
        float4 bv = *(const float4*)(Bptr + k0);
        As[acol + 0][arow] = av.x;
        As[acol + 1][arow] = av.y;
        As[acol + 2][arow] = av.z;
        As[acol + 3][arow] = av.w;
        Bs[acol + 0][arow] = bv.x;
        Bs[acol + 1][arow] = bv.y;
        Bs[acol + 2][arow] = bv.z;
        Bs[acol + 3][arow] = bv.w;
        __syncthreads();

        #pragma unroll
        for (int kk = 0; kk < GBK; kk++) {
            float4 a0 = *(const float4*)&As[kk][ty * 8];
            float4 a1 = *(const float4*)&As[kk][ty * 8 + 4];
            float4 b0 = *(const float4*)&Bs[kk][tx * 8];
            float4 b1 = *(const float4*)&Bs[kk][tx * 8 + 4];
            float a[8] = {a0.x, a0.y, a0.z, a0.w, a1.x, a1.y, a1.z, a1.w};
            float b[8] = {b0.x, b0.y, b0.z, b0.w, b1.x, b1.y, b1.z, b1.w};
            #pragma unroll
            for (int i = 0; i < 8; i++)
                #pragma unroll
                for (int j = 0; j < 8; j++)
                    acc[i][j] = fmaf(a[i], b[j], acc[i][j]);
        }
        __syncthreads();
    }

    // epilogue
    #pragma unroll
    for (int i = 0; i < 8; i++) {
        size_t row = (size_t)(bm + ty * 8 + i);
        float* crow = C + row * N + bn + tx * 8;
        const float* rrow = (EPI == 2) ? (R + row * N + bn + tx * 8) : nullptr;
        float vals[8];
        #pragma unroll
        for (int j = 0; j < 8; j++) {
            float v = acc[i][j];
            if (EPI == 1) {
                // exact erf GELU
                v = 0.5f * v * (1.0f + erff(v * 0.70710678118654752f));
            } else if (EPI == 2) {
                v += rrow[j];
            }
            vals[j] = v;
        }
        *(float4*)(crow)     = make_float4(vals[0], vals[1], vals[2], vals[3]);
        *(float4*)(crow + 4) = make_float4(vals[4], vals[5], vals[6], vals[7]);
    }
}

// ---------------------------------------------------------------------------
// Causal flash attention (fp32). Layout of Q/K/V/O: [B, L, H, DH] (= [M, D]).
// Grid: (L/64, B*H). 256 threads. 64-query x 64-key tiles, online softmax.
// ---------------------------------------------------------------------------
#define AQP 132   // padded row length for 128-wide tiles (bank-conflict pad)

__global__ __launch_bounds__(256) void attn_kernel(
    const float* __restrict__ Qg, const float* __restrict__ Kg,
    const float* __restrict__ Vg, float* __restrict__ Og)
{
    extern __shared__ float sm[];
    float* Qs   = sm;                    // 64*132
    float* Ks   = Qs + 64 * AQP;         // 64*132
    float* Vs   = Ks + 64 * AQP;         // 64*132
    float* Ps   = Vs + 64 * AQP;         // 64*65
    float* mrow = Ps + 64 * 65;          // 64
    float* lrow = mrow + 64;             // 64
    float* arow = lrow + 64;             // 64

    const int tid = threadIdx.x;
    const int bh  = blockIdx.y;
    const int b   = bh >> 4;
    const int h   = bh & 15;
    const int q0  = blockIdx.x * 64;

    const size_t base = ((size_t)b * KL) * KD + (size_t)h * KDH;
    const float* Qb = Qg + base;
    const float* Kb = Kg + base;
    const float* Vb = Vg + base;

    // Load Q tile [64,128]
    #pragma unroll
    for (int r = 0; r < 8; r++) {
        int idx = tid + r * 256;          // 0..2047
        int row = idx >> 5;
        int c4  = (idx & 31) * 4;
        *(float4*)(Qs + row * AQP + c4) =
            *(const float4*)(Qb + (size_t)(q0 + row) * KD + c4);
    }
    if (tid < 64) { mrow[tid] = -1e30f; lrow[tid] = 0.f; }

    const int ty = tid >> 4;   // 0..15 -> S rows ty*4..ty*4+3 ; O rows same
    const int tx = tid & 15;   // 0..15 -> S cols tx*4..tx*4+3 ; O cols tx*8..+7

    float oacc[4][8];
    #pragma unroll
    for (int i = 0; i < 4; i++)
        #pragma unroll
        for (int j = 0; j < 8; j++) oacc[i][j] = 0.f;

    const float scale = 0.08838834764831845f;   // 1/sqrt(128)
    const int nkt = q0 / 64 + 1;

    for (int kt = 0; kt < nkt; kt++) {
        const int k0 = kt * 64;
        __syncthreads();   // prior iteration's P@V done before overwriting K/V
        #pragma unroll
        for (int r = 0; r < 8; r++) {
            int idx = tid + r * 256;
            int row = idx >> 5;
            int c4  = (idx & 31) * 4;
            *(float4*)(Ks + row * AQP + c4) =
                *(const float4*)(Kb + (size_t)(k0 + row) * KD + c4);
            *(float4*)(Vs + row * AQP + c4) =
                *(const float4*)(Vb + (size_t)(k0 + row) * KD + c4);
        }
        __syncthreads();

        // S[64,64] = Q K^T, 4x4 per thread
        float s[4][4];
        #pragma unroll
        for (int i = 0; i < 4; i++)
            #pragma unroll
            for (int j = 0; j < 4; j++) s[i][j] = 0.f;

        for (int d = 0; d < KDH; d += 4) {
            float4 qv[4], kv[4];
            #pragma unroll
            for (int i = 0; i < 4; i++)
                qv[i] = *(const float4*)(Qs + (ty * 4 + i) * AQP + d);
            #pragma unroll
            for (int j = 0; j < 4; j++)
                kv[j] = *(const float4*)(Ks + (tx * 4 + j) * AQP + d);
            #pragma unroll
            for (int i = 0; i < 4; i++)
                #pragma unroll
                for (int j = 0; j < 4; j++) {
                    s[i][j] = fmaf(qv[i].x, kv[j].x, s[i][j]);
                    s[i][j] = fmaf(qv[i].y, kv[j].y, s[i][j]);
                    s[i][j] = fmaf(qv[i].z, kv[j].z, s[i][j]);
                    s[i][j] = fmaf(qv[i].w, kv[j].w, s[i][j]);
                }
        }

        // scale + causal mask + store to Ps
        #pragma unroll
        for (int i = 0; i < 4; i++) {
            int qr = q0 + ty * 4 + i;
            #pragma unroll
            for (int j = 0; j < 4; j++) {
                int kc = k0 + tx * 4 + j;
                float v = s[i][j] * scale;
                if (kc > qr) v = -1e30f;
                Ps[(ty * 4 + i) * 65 + (tx * 4 + j)] = v;
            }
        }
        __syncthreads();

        // per-row online softmax (threads 0..63 each own one row)
        if (tid < 64) {
            float mo = mrow[tid];
            float mx = mo;
            #pragma unroll 8
            for (int s2 = 0; s2 < 64; s2++)
                mx = fmaxf(mx, Ps[tid * 65 + s2]);
            float alpha = __expf(mo - mx);
            float sum = 0.f;
            #pragma unroll 8
            for (int s2 = 0; s2 < 64; s2++) {
                float p = __expf(Ps[tid * 65 + s2] - mx);
                Ps[tid * 65 + s2] = p;
                sum += p;
            }
            mrow[tid] = mx;
            lrow[tid] = lrow[tid] * alpha + sum;
            arow[tid] = alpha;
        }
        __syncthreads();

        // O = O*alpha + P @ V   (4 rows x 8 cols per thread)
        float al[4];
        #pragma unroll
        for (int i = 0; i < 4; i++) al[i] = arow[ty * 4 + i];
        #pragma unroll
        for (int i = 0; i < 4; i++)
            #pragma unroll
            for (int j = 0; j < 8; j++) oacc[i][j] *= al[i];

        for (int sK = 0; sK < 64; sK++) {
            float p[4];
            #pragma unroll
            for (int i = 0; i < 4; i++) p[i] = Ps[(ty * 4 + i) * 65 + sK];
            float4 v0 = *(const float4*)(Vs + sK * AQP + tx * 8);
            float4 v1 = *(const float4*)(Vs + sK * AQP + tx * 8 + 4);
            float vv[8] = {v0.x, v0.y, v0.z, v0.w, v1.x, v1.y, v1.z, v1.w};
            #pragma unroll
            for (int i = 0; i < 4; i++)
                #pragma unroll
                for (int j = 0; j < 8; j++)
                    oacc[i][j] = fmaf(p[i], vv[j], oacc[i][j]);
        }
    }
    __syncthreads();

    float invl[4];
    #pragma unroll
    for (int i = 0; i < 4; i++) invl[i] = 1.0f / lrow[ty * 4 + i];

    float* Ob = Og + ((size_t)b * KL + q0) * KD + (size_t)h * KDH;
    #pragma unroll
    for (int i = 0; i < 4; i++) {
        float* orow = Ob + (size_t)(ty * 4 + i) * KD + tx * 8;
        *(float4*)(orow) = make_float4(oacc[i][0] * invl[i], oacc[i][1] * invl[i],
                                       oacc[i][2] * invl[i], oacc[i][3] * invl[i]);
        *(float4*)(orow + 4) = make_float4(oacc[i][4] * invl[i], oacc[i][5] * invl[i],
                                           oacc[i][6] * invl[i], oacc[i][7] * invl[i]);
    }
}

// ---------------------------------------------------------------------------
// kernel_launch
// inputs: 0 x, 1 mask(unused, causal applied analytically), 2 ln1_w, 3 wq,
//         4 wk, 5 wv, 6 wo, 7 ln2_w, 8 w_up, 9 w_down
// ---------------------------------------------------------------------------
extern "C" void kernel_launch(void* const* d_in, const int* in_sizes, int n_in,
                              void* d_out, int out_size)
{
    const float* x    = (const float*)d_in[0];
    const float* ln1  = (const float*)d_in[2];
    const float* wq   = (const float*)d_in[3];
    const float* wk   = (const float*)d_in[4];
    const float* wv   = (const float*)d_in[5];
    const float* wo   = (const float*)d_in[6];
    const float* ln2  = (const float*)d_in[7];
    const float* wup  = (const float*)d_in[8];
    const float* wdn  = (const float*)d_in[9];
    float* out = (float*)d_out;

    float *h, *q, *k, *v, *o, *u;
    cudaGetSymbolAddress((void**)&h, g_h);
    cudaGetSymbolAddress((void**)&q, g_q);
    cudaGetSymbolAddress((void**)&k, g_k);
    cudaGetSymbolAddress((void**)&v, g_v);
    cudaGetSymbolAddress((void**)&o, g_o);
    cudaGetSymbolAddress((void**)&u, g_u);

    // attention smem: 3*64*132 + 64*65 + 3*64 floats
    const int attn_smem = (3 * 64 * AQP + 64 * 65 + 3 * 64) * (int)sizeof(float);
    cudaFuncSetAttribute(attn_kernel,
                         cudaFuncAttributeMaxDynamicSharedMemorySize, attn_smem);

    dim3 blk(256);

    // 1. h = rmsnorm(x, ln1)
    rmsnorm_kernel<<<KM, blk>>>(x, ln1, h);

    // 2. q/k/v = h @ W^T
    dim3 gqkv(KD / GBN, KM / GBM);
    gemm_nt_kernel<0><<<gqkv, blk>>>(h, wq, q, nullptr, KM, KD, KD);
    gemm_nt_kernel<0><<<gqkv, blk>>>(h, wk, k, nullptr, KM, KD, KD);
    gemm_nt_kernel<0><<<gqkv, blk>>>(h, wv, v, nullptr, KM, KD, KD);

    // 3. o = causal_attention(q, k, v)
    dim3 gattn(KL / 64, KB * KH);
    attn_kernel<<<gattn, blk, attn_smem>>>(q, k, v, o);

    // 4. out = x + o @ wo^T
    gemm_nt_kernel<2><<<gqkv, blk>>>(o, wo, out, x, KM, KD, KD);

    // 5. h = rmsnorm(out, ln2)
    rmsnorm_kernel<<<KM, blk>>>(out, ln2, h);

    // 6. u = gelu(h @ wup^T)
    dim3 gup(KDFF / GBN, KM / GBM);
    gemm_nt_kernel<1><<<gup, blk>>>(h, wup, u, nullptr, KM, KDFF, KD);

    // 7. out = out + u @ wdn^T
    gemm_nt_kernel<2><<<gqkv, blk>>>(u, wdn, out, out, KM, KD, KDFF);
}

// round 4
// speedup vs baseline: 2.3808x; 2.3808x over previous
#include <cuda_runtime.h>
#include <cuda_bf16.h>
#include <math.h>
#include <stdint.h>

// ---------------------------------------------------------------------------
// TransformerBlock  B=2, L=2048, D=2048, H=16, DH=128, DFF=8192
// Round 3: mma.sync (HMMA) bf16 hi/lo-split GEMMs — tcgen05 is unavailable
// because the harness emits compute_103 (non-'a') PTX. cp.async 3-stage
// pipeline + ldmatrix + m16n8k16 bf16. fp32 flash attention unchanged.
// ---------------------------------------------------------------------------

#define KB   2
#define KL   2048
#define KD   2048
#define KH   16
#define KDH  128
#define KDFF 8192
#define KM   (KB * KL)   // 4096 rows

// ----------------------------- PTX helpers --------------------------------
__device__ __forceinline__ uint32_t smem_u32(const void* p) {
    uint32_t a;
    asm("{ .reg .u64 t; cvta.to.shared.u64 t, %1; cvt.u32.u64 %0, t; }"
        : "=r"(a) : "l"(p));
    return a;
}

// Swizzle<2,4,3> for 64B rows: XOR 16B-chunk bits[5:4] with row bits[8:7]
#define SWZ64(off) ((off) ^ (((off) >> 3) & 0x30))

#define CP_ASYNC16(smem, gptr) \
    asm volatile("cp.async.cg.shared.global [%0], [%1], 16;" \
        :: "r"((uint32_t)(smem)), "l"(gptr) : "memory")
#define CP_COMMIT() asm volatile("cp.async.commit_group;" ::: "memory")
#define CP_WAIT2()  asm volatile("cp.async.wait_group 2;" ::: "memory")

#define LDSM_X4(r, addr) \
    asm volatile("ldmatrix.sync.aligned.m8n8.x4.shared.b16 {%0,%1,%2,%3}, [%4];" \
        : "=r"((r)[0]), "=r"((r)[1]), "=r"((r)[2]), "=r"((r)[3]) \
        : "r"((uint32_t)(addr)))

__device__ __forceinline__ void mma_bf16(float* c, const uint32_t* a,
                                         uint32_t b0, uint32_t b1) {
    asm volatile(
        "mma.sync.aligned.m16n8k16.row.col.f32.bf16.bf16.f32 "
        "{%0,%1,%2,%3}, {%4,%5,%6,%7}, {%8,%9}, {%0,%1,%2,%3};"
        : "+f"(c[0]), "+f"(c[1]), "+f"(c[2]), "+f"(c[3])
        : "r"(a[0]), "r"(a[1]), "r"(a[2]), "r"(a[3]), "r"(b0), "r"(b1));
}

__device__ __forceinline__ void split2(float v, __nv_bfloat16& h, __nv_bfloat16& l) {
    h = __float2bfloat16(v);
    l = __float2bfloat16(v - __bfloat162float(h));
}

// ------------------------------- scratch ----------------------------------
__device__ __nv_bfloat16 g_wq_h[(size_t)KD * KD];
__device__ __nv_bfloat16 g_wq_l[(size_t)KD * KD];
__device__ __nv_bfloat16 g_wk_h[(size_t)KD * KD];
__device__ __nv_bfloat16 g_wk_l[(size_t)KD * KD];
__device__ __nv_bfloat16 g_wv_h[(size_t)KD * KD];
__device__ __nv_bfloat16 g_wv_l[(size_t)KD * KD];
__device__ __nv_bfloat16 g_wo_h[(size_t)KD * KD];
__device__ __nv_bfloat16 g_wo_l[(size_t)KD * KD];
__device__ __nv_bfloat16 g_wu_h[(size_t)KDFF * KD];
__device__ __nv_bfloat16 g_wu_l[(size_t)KDFF * KD];
__device__ __nv_bfloat16 g_wd_h[(size_t)KD * KDFF];
__device__ __nv_bfloat16 g_wd_l[(size_t)KD * KDFF];
__device__ __nv_bfloat16 g_h_h[(size_t)KM * KD];
__device__ __nv_bfloat16 g_h_l[(size_t)KM * KD];
__device__ __nv_bfloat16 g_o_h[(size_t)KM * KD];
__device__ __nv_bfloat16 g_o_l[(size_t)KM * KD];
__device__ __nv_bfloat16 g_u_h[(size_t)KM * KDFF];
__device__ __nv_bfloat16 g_u_l[(size_t)KM * KDFF];
__device__ float g_q[(size_t)KM * KD];
__device__ float g_k[(size_t)KM * KD];
__device__ float g_v[(size_t)KM * KD];

// ---------------------------------------------------------------------------
// weight split: fp32 -> bf16 hi + bf16 lo
// ---------------------------------------------------------------------------
__global__ __launch_bounds__(256) void split_kernel(
    const float* __restrict__ src, __nv_bfloat16* __restrict__ hi,
    __nv_bfloat16* __restrict__ lo, int n4)
{
    int i = blockIdx.x * 256 + threadIdx.x;
    if (i >= n4) return;
    float4 v = ((const float4*)src)[i];
    __nv_bfloat16 h[4], l[4];
    split2(v.x, h[0], l[0]); split2(v.y, h[1], l[1]);
    split2(v.z, h[2], l[2]); split2(v.w, h[3], l[3]);
    ((uint2*)hi)[i] = *(uint2*)h;
    ((uint2*)lo)[i] = *(uint2*)l;
}

// ---------------------------------------------------------------------------
// RMSNorm with fused hi/lo split output
// ---------------------------------------------------------------------------
__global__ __launch_bounds__(256) void rmsnorm_split_kernel(
    const float* __restrict__ x, const float* __restrict__ w,
    __nv_bfloat16* __restrict__ yh, __nv_bfloat16* __restrict__ yl)
{
    int row = blockIdx.x;
    const float* xr = x + (size_t)row * KD;
    float s = 0.f;
    #pragma unroll
    for (int i = threadIdx.x; i < KD; i += 256) { float v = xr[i]; s += v * v; }
    __shared__ float red[256];
    red[threadIdx.x] = s;
    __syncthreads();
    #pragma unroll
    for (int st = 128; st > 0; st >>= 1) {
        if (threadIdx.x < st) red[threadIdx.x] += red[threadIdx.x + st];
        __syncthreads();
    }
    float inv = rsqrtf(red[0] * (1.0f / KD) + 1e-8f);
    #pragma unroll
    for (int i = threadIdx.x; i < KD; i += 256) {
        float v = xr[i] * inv * w[i];
        __nv_bfloat16 h, l;
        split2(v, h, l);
        yh[(size_t)row * KD + i] = h;
        yl[(size_t)row * KD + i] = l;
    }
}

// ---------------------------------------------------------------------------
// HMMA split-bf16 GEMM:  C[M,N] = A[M,K] @ Bw[N,K]^T
//   C = Ah Bh^T + Ah Bl^T + Al Bh^T (fp32 accum)
// CTA tile 128x256, 8 warps (2x4), warp tile 64x64, K-chunk 32,
// 3-stage cp.async pipeline. EPI: 0 fp32, 1 GELU->hi/lo bf16, 2 C = R + acc.
// ---------------------------------------------------------------------------
#define TM 128
#define TN 256
#define TKC 32
#define ASPLIT 8192u            // bytes per A split per stage (128*32*2)
#define BSPLIT 16384u           // bytes per B split per stage (256*32*2)
#define STAGE  (2u*ASPLIT + 2u*BSPLIT)   // 49152
#define NSTAGE 3
#define GEMM_SMEM (NSTAGE * STAGE)       // 147456

template<int EPI>
__global__ __launch_bounds__(256, 1) void gemm_mma_kernel(
    const __nv_bfloat16* __restrict__ Ah, const __nv_bfloat16* __restrict__ Al,
    const __nv_bfloat16* __restrict__ Bh, const __nv_bfloat16* __restrict__ Bl,
    float* __restrict__ C, const float* __restrict__ R,
    __nv_bfloat16* __restrict__ Chi, __nv_bfloat16* __restrict__ Clo,
    int N, int K)
{
    extern __shared__ char smem[];
    const uint32_t sb = smem_u32(smem);
    const int tid  = threadIdx.x;
    const int wid  = tid >> 5;
    const int lane = tid & 31;
    const int wm   = wid & 1;        // 0..1 -> m offset
    const int wn   = wid >> 1;       // 0..3 -> n offset
    const int bm   = blockIdx.y * TM;
    const int bn   = blockIdx.x * TN;

    const int NC = K / TKC;

    // per-thread ldmatrix address components
    const int mat  = lane >> 3;      // 0..3
    const int rin  = lane & 7;
    const int rowA = (mat & 1) * 8 + rin;   // within m16 tile
    const int kA   = mat >> 1;              // 16B chunk within k16
    const int rowB = (mat >> 1) * 8 + rin;  // within n16 pair
    const int kB   = mat & 1;

    float acc[4][8][4];
    #pragma unroll
    for (int i = 0; i < 4; i++)
        #pragma unroll
        for (int j = 0; j < 8; j++)
            #pragma unroll
            for (int t = 0; t < 4; t++) acc[i][j][t] = 0.f;

    // ---- stage loader ----
    auto load_stage = [&](int c, int s) {
        const int kc = c * TKC;
        const uint32_t base = sb + (uint32_t)s * STAGE;
        #pragma unroll
        for (int i = 0; i < 2; i++) {
            int chunk = i * 256 + tid;      // 0..511
            int r = chunk >> 2, cc = chunk & 3;
            uint32_t so = SWZ64((uint32_t)(r * 64 + cc * 16));
            size_t go = (size_t)(bm + r) * K + kc + cc * 8;
            CP_ASYNC16(base + so,           Ah + go);
            CP_ASYNC16(base + ASPLIT + so,  Al + go);
        }
        #pragma unroll
        for (int i = 0; i < 4; i++) {
            int chunk = i * 256 + tid;      // 0..1023
            int r = chunk >> 2, cc = chunk & 3;
            uint32_t so = SWZ64((uint32_t)(r * 64 + cc * 16));
            size_t go = (size_t)(bn + r) * K + kc + cc * 8;
            CP_ASYNC16(base + 2u*ASPLIT + so,          Bh + go);
            CP_ASYNC16(base + 2u*ASPLIT + BSPLIT + so, Bl + go);
        }
        CP_COMMIT();
    };

    load_stage(0, 0);
    if (NC > 1) load_stage(1, 1); else CP_COMMIT();

    for (int c = 0; c < NC; c++) {
        const int s = c % NSTAGE;
        if (c + 2 < NC) load_stage(c + 2, (c + 2) % NSTAGE);
        else            CP_COMMIT();
        CP_WAIT2();
        __syncthreads();

        const uint32_t sAh = sb + (uint32_t)s * STAGE;
        const uint32_t sAl = sAh + ASPLIT;
        const uint32_t sBh = sAl + ASPLIT;
        const uint32_t sBl = sBh + BSPLIT;

        #pragma unroll
        for (int h = 0; h < 2; h++) {
            uint32_t afh[4][4], afl[4][4], bfh[4][4], bfl[4][4];
            #pragma unroll
            for (int mi = 0; mi < 4; mi++) {
                int m = wm * 64 + mi * 16 + rowA;
                uint32_t off = SWZ64((uint32_t)(m * 64 + (h * 2 + kA) * 16));
                LDSM_X4(afh[mi], sAh + off);
                LDSM_X4(afl[mi], sAl + off);
            }
            #pragma unroll
            for (int nj = 0; nj < 4; nj++) {
                int n = wn * 64 + nj * 16 + rowB;
                uint32_t off = SWZ64((uint32_t)(n * 64 + (h * 2 + kB) * 16));
                LDSM_X4(bfh[nj], sBh + off);
                LDSM_X4(bfl[nj], sBl + off);
            }
            #pragma unroll
            for (int mi = 0; mi < 4; mi++)
                #pragma unroll
                for (int nj = 0; nj < 4; nj++)
                    #pragma unroll
                    for (int hf = 0; hf < 2; hf++) {
                        float* cc = acc[mi][nj * 2 + hf];
                        mma_bf16(cc, afh[mi], bfh[nj][hf*2], bfh[nj][hf*2+1]);
                        mma_bf16(cc, afh[mi], bfl[nj][hf*2], bfl[nj][hf*2+1]);
                        mma_bf16(cc, afl[mi], bfh[nj][hf*2], bfh[nj][hf*2+1]);
                    }
        }
        __syncthreads();
    }

    // ---- epilogue ----
    #pragma unroll
    for (int mi = 0; mi < 4; mi++) {
        const int row0 = bm + wm * 64 + mi * 16 + (lane >> 2);
        #pragma unroll
        for (int f = 0; f < 8; f++) {
            const int n0 = bn + wn * 64 + f * 8 + (lane & 3) * 2;
            float* cc = acc[mi][f];
            #pragma unroll
            for (int hrow = 0; hrow < 2; hrow++) {
                const int row = row0 + hrow * 8;
                float v0 = cc[hrow * 2 + 0];
                float v1 = cc[hrow * 2 + 1];
                const size_t idx = (size_t)row * N + n0;
                if (EPI == 1) {
                    v0 = 0.5f * v0 * (1.0f + erff(v0 * 0.70710678118654752f));
                    v1 = 0.5f * v1 * (1.0f + erff(v1 * 0.70710678118654752f));
                    __nv_bfloat16 h0, l0, h1, l1;
                    split2(v0, h0, l0); split2(v1, h1, l1);
                    __nv_bfloat162 hp; hp.x = h0; hp.y = h1;
                    __nv_bfloat162 lp; lp.x = l0; lp.y = l1;
                    *(__nv_bfloat162*)(Chi + idx) = hp;
                    *(__nv_bfloat162*)(Clo + idx) = lp;
                } else {
                    if (EPI == 2) {
                        float2 rv = *(const float2*)(R + idx);
                        v0 += rv.x; v1 += rv.y;
                    }
                    float2 ov; ov.x = v0; ov.y = v1;
                    *(float2*)(C + idx) = ov;
                }
            }
        }
    }
}

// ---------------------------------------------------------------------------
// Causal flash attention (fp32 math), outputs hi/lo bf16 split of O.
// Q/K/V layout [B,L,H,DH] = [M, 2048]. Grid: (L/64, B*H), 256 threads.
// ---------------------------------------------------------------------------
#define AQP 132

__global__ __launch_bounds__(256) void attn_kernel(
    const float* __restrict__ Qg, const float* __restrict__ Kg,
    const float* __restrict__ Vg,
    __nv_bfloat16* __restrict__ Oh, __nv_bfloat16* __restrict__ Ol)
{
    extern __shared__ float sm[];
    float* Qs   = sm;
    float* Ks   = Qs + 64 * AQP;
    float* Vs   = Ks + 64 * AQP;
    float* Ps   = Vs + 64 * AQP;
    float* mrow = Ps + 64 * 65;
    float* lrow = mrow + 64;
    float* arow = lrow + 64;

    const int tid = threadIdx.x;
    const int bh  = blockIdx.y;
    const int b   = bh >> 4;
    const int h   = bh & 15;
    const int q0  = blockIdx.x * 64;

    const size_t base = ((size_t)b * KL) * KD + (size_t)h * KDH;
    const float* Qb = Qg + base;
    const float* Kb = Kg + base;
    const float* Vb = Vg + base;

    #pragma unroll
    for (int r = 0; r < 8; r++) {
        int idx = tid + r * 256;
        int row = idx >> 5;
        int c4  = (idx & 31) * 4;
        *(float4*)(Qs + row * AQP + c4) =
            *(const float4*)(Qb + (size_t)(q0 + row) * KD + c4);
    }
    if (tid < 64) { mrow[tid] = -1e30f; lrow[tid] = 0.f; }

    const int ty = tid >> 4;
    const int tx = tid & 15;

    float oacc[4][8];
    #pragma unroll
    for (int i = 0; i < 4; i++)
        #pragma unroll
        for (int j = 0; j < 8; j++) oacc[i][j] = 0.f;

    const float scale = 0.08838834764831845f;
    const int nkt = q0 / 64 + 1;

    for (int kt = 0; kt < nkt; kt++) {
        const int k0 = kt * 64;
        __syncthreads();
        #pragma unroll
        for (int r = 0; r < 8; r++) {
            int idx = tid + r * 256;
            int row = idx >> 5;
            int c4  = (idx & 31) * 4;
            *(float4*)(Ks + row * AQP + c4) =
                *(const float4*)(Kb + (size_t)(k0 + row) * KD + c4);
            *(float4*)(Vs + row * AQP + c4) =
                *(const float4*)(Vb + (size_t)(k0 + row) * KD + c4);
        }
        __syncthreads();

        float s[4][4];
        #pragma unroll
        for (int i = 0; i < 4; i++)
            #pragma unroll
            for (int j = 0; j < 4; j++) s[i][j] = 0.f;

        for (int d = 0; d < KDH; d += 4) {
            float4 qv[4], kv[4];
            #pragma unroll
            for (int i = 0; i < 4; i++)
                qv[i] = *(const float4*)(Qs + (ty * 4 + i) * AQP + d);
            #pragma unroll
            for (int j = 0; j < 4; j++)
                kv[j] = *(const float4*)(Ks + (tx * 4 + j) * AQP + d);
            #pragma unroll
            for (int i = 0; i < 4; i++)
                #pragma unroll
                for (int j = 0; j < 4; j++) {
                    s[i][j] = fmaf(qv[i].x, kv[j].x, s[i][j]);
                    s[i][j] = fmaf(qv[i].y, kv[j].y, s[i][j]);
                    s[i][j] = fmaf(qv[i].z, kv[j].z, s[i][j]);
                    s[i][j] = fmaf(qv[i].w, kv[j].w, s[i][j]);
                }
        }

        #pragma unroll
        for (int i = 0; i < 4; i++) {
            int qr = q0 + ty * 4 + i;
            #pragma unroll
            for (int j = 0; j < 4; j++) {
                int kc = k0 + tx * 4 + j;
                float v = s[i][j] * scale;
                if (kc > qr) v = -1e30f;
                Ps[(ty * 4 + i) * 65 + (tx * 4 + j)] = v;
            }
        }
        __syncthreads();

        if (tid < 64) {
            float mo = mrow[tid];
            float mx = mo;
            #pragma unroll 8
            for (int s2 = 0; s2 < 64; s2++)
                mx = fmaxf(mx, Ps[tid * 65 + s2]);
            float alpha = __expf(mo - mx);
            float sum = 0.f;
            #pragma unroll 8
            for (int s2 = 0; s2 < 64; s2++) {
                float p = __expf(Ps[tid * 65 + s2] - mx);
                Ps[tid * 65 + s2] = p;
                sum += p;
            }
            mrow[tid] = mx;
            lrow[tid] = lrow[tid] * alpha + sum;
            arow[tid] = alpha;
        }
        __syncthreads();

        float al[4];
        #pragma unroll
        for (int i = 0; i < 4; i++) al[i] = arow[ty * 4 + i];
        #pragma unroll
        for (int i = 0; i < 4; i++)
            #pragma unroll
            for (int j = 0; j < 8; j++) oacc[i][j] *= al[i];

        for (int sK = 0; sK < 64; sK++) {
            float p[4];
            #pragma unroll
            for (int i = 0; i < 4; i++) p[i] = Ps[(ty * 4 + i) * 65 + sK];
            float4 v0 = *(const float4*)(Vs + sK * AQP + tx * 8);
            float4 v1 = *(const float4*)(Vs + sK * AQP + tx * 8 + 4);
            float vv[8] = {v0.x, v0.y, v0.z, v0.w, v1.x, v1.y, v1.z, v1.w};
            #pragma unroll
            for (int i = 0; i < 4; i++)
                #pragma unroll
                for (int j = 0; j < 8; j++)
                    oacc[i][j] = fmaf(p[i], vv[j], oacc[i][j]);
        }
    }
    __syncthreads();

    float invl[4];
    #pragma unroll
    for (int i = 0; i < 4; i++) invl[i] = 1.0f / lrow[ty * 4 + i];

    const size_t obase = ((size_t)b * KL + q0) * KD + (size_t)h * KDH;
    #pragma unroll
    for (int i = 0; i < 4; i++) {
        __nv_bfloat16 hh[8], ll[8];
        #pragma unroll
        for (int j = 0; j < 8; j++)
            split2(oacc[i][j] * invl[i], hh[j], ll[j]);
        size_t off = obase + (size_t)(ty * 4 + i) * KD + tx * 8;
        *(uint4*)(Oh + off) = *(uint4*)hh;
        *(uint4*)(Ol + off) = *(uint4*)ll;
    }
}

// ---------------------------------------------------------------------------
// kernel_launch
// inputs: 0 x, 1 mask(unused), 2 ln1_w, 3 wq, 4 wk, 5 wv, 6 wo, 7 ln2_w,
//         8 w_up, 9 w_down
// ---------------------------------------------------------------------------
extern "C" void kernel_launch(void* const* d_in, const int* in_sizes, int n_in,
                              void* d_out, int out_size)
{
    const float* x    = (const float*)d_in[0];
    const float* ln1  = (const float*)d_in[2];
    const float* wq   = (const float*)d_in[3];
    const float* wk   = (const float*)d_in[4];
    const float* wv   = (const float*)d_in[5];
    const float* wo   = (const float*)d_in[6];
    const float* ln2  = (const float*)d_in[7];
    const float* wup  = (const float*)d_in[8];
    const float* wdn  = (const float*)d_in[9];
    float* out = (float*)d_out;

    __nv_bfloat16 *wq_h,*wq_l,*wk_h,*wk_l,*wv_h,*wv_l,*wo_h,*wo_l;
    __nv_bfloat16 *wu_h,*wu_l,*wd_h,*wd_l,*h_h,*h_l,*o_h,*o_l,*u_h,*u_l;
    float *q,*k,*v;
    cudaGetSymbolAddress((void**)&wq_h, g_wq_h);
    cudaGetSymbolAddress((void**)&wq_l, g_wq_l);
    cudaGetSymbolAddress((void**)&wk_h, g_wk_h);
    cudaGetSymbolAddress((void**)&wk_l, g_wk_l);
    cudaGetSymbolAddress((void**)&wv_h, g_wv_h);
    cudaGetSymbolAddress((void**)&wv_l, g_wv_l);
    cudaGetSymbolAddress((void**)&wo_h, g_wo_h);
    cudaGetSymbolAddress((void**)&wo_l, g_wo_l);
    cudaGetSymbolAddress((void**)&wu_h, g_wu_h);
    cudaGetSymbolAddress((void**)&wu_l, g_wu_l);
    cudaGetSymbolAddress((void**)&wd_h, g_wd_h);
    cudaGetSymbolAddress((void**)&wd_l, g_wd_l);
    cudaGetSymbolAddress((void**)&h_h, g_h_h);
    cudaGetSymbolAddress((void**)&h_l, g_h_l);
    cudaGetSymbolAddress((void**)&o_h, g_o_h);
    cudaGetSymbolAddress((void**)&o_l, g_o_l);
    cudaGetSymbolAddress((void**)&u_h, g_u_h);
    cudaGetSymbolAddress((void**)&u_l, g_u_l);
    cudaGetSymbolAddress((void**)&q, g_q);
    cudaGetSymbolAddress((void**)&k, g_k);
    cudaGetSymbolAddress((void**)&v, g_v);

    cudaFuncSetAttribute(gemm_mma_kernel<0>, cudaFuncAttributeMaxDynamicSharedMemorySize, GEMM_SMEM);
    cudaFuncSetAttribute(gemm_mma_kernel<1>, cudaFuncAttributeMaxDynamicSharedMemorySize, GEMM_SMEM);
    cudaFuncSetAttribute(gemm_mma_kernel<2>, cudaFuncAttributeMaxDynamicSharedMemorySize, GEMM_SMEM);
    const int attn_smem = (3 * 64 * AQP + 64 * 65 + 3 * 64) * (int)sizeof(float);
    cudaFuncSetAttribute(attn_kernel, cudaFuncAttributeMaxDynamicSharedMemorySize, attn_smem);

    dim3 blk(256);

    // weight splits
    {
        int n4 = KD * KD / 4;
        int g4 = (n4 + 255) / 256;
        split_kernel<<<g4, blk>>>(wq, wq_h, wq_l, n4);
        split_kernel<<<g4, blk>>>(wk, wk_h, wk_l, n4);
        split_kernel<<<g4, blk>>>(wv, wv_h, wv_l, n4);
        split_kernel<<<g4, blk>>>(wo, wo_h, wo_l, n4);
        int n4f = KDFF * KD / 4;
        int g4f = (n4f + 255) / 256;
        split_kernel<<<g4f, blk>>>(wup, wu_h, wu_l, n4f);
        split_kernel<<<g4f, blk>>>(wdn, wd_h, wd_l, n4f);
    }

    // 1. h = rmsnorm(x, ln1) -> hi/lo
    rmsnorm_split_kernel<<<KM, blk>>>(x, ln1, h_h, h_l);

    // 2. q/k/v = h @ W^T (fp32 out)
    dim3 gqkv(KD / TN, KM / TM);
    gemm_mma_kernel<0><<<gqkv, blk, GEMM_SMEM>>>(h_h, h_l, wq_h, wq_l, q, nullptr, nullptr, nullptr, KD, KD);
    gemm_mma_kernel<0><<<gqkv, blk, GEMM_SMEM>>>(h_h, h_l, wk_h, wk_l, k, nullptr, nullptr, nullptr, KD, KD);
    gemm_mma_kernel<0><<<gqkv, blk, GEMM_SMEM>>>(h_h, h_l, wv_h, wv_l, v, nullptr, nullptr, nullptr, KD, KD);

    // 3. o = causal_attention(q,k,v) -> hi/lo
    dim3 gattn(KL / 64, KB * KH);
    attn_kernel<<<gattn, blk, attn_smem>>>(q, k, v, o_h, o_l);

    // 4. out = x + o @ wo^T
    gemm_mma_kernel<2><<<gqkv, blk, GEMM_SMEM>>>(o_h, o_l, wo_h, wo_l, out, x, nullptr, nullptr, KD, KD);

    // 5. h = rmsnorm(out, ln2) -> hi/lo
    rmsnorm_split_kernel<<<KM, blk>>>(out, ln2, h_h, h_l);

    // 6. u = gelu(h @ wup^T) -> hi/lo
    dim3 gup(KDFF / TN, KM / TM);
    gemm_mma_kernel<1><<<gup, blk, GEMM_SMEM>>>(h_h, h_l, wu_h, wu_l, nullptr, nullptr, u_h, u_l, KDFF, KD);

    // 7. out = out + u @ wdn^T
    gemm_mma_kernel<2><<<gqkv, blk, GEMM_SMEM>>>(u_h, u_l, wd_h, wd_l, out, out, nullptr, nullptr, KD, KDFF);
}

// round 5
// speedup vs baseline: 2.9842x; 1.2534x over previous
#include <cuda_runtime.h>
#include <cuda_bf16.h>
#include <math.h>
#include <stdint.h>

// ---------------------------------------------------------------------------
// TransformerBlock  B=2, L=2048, D=2048, H=16, DH=128, DFF=8192
// Round 4: HMMA split-bf16 GEMMs + HMMA split-bf16 flash attention (FA2-style
// register softmax). All GEMM-class math on tensor cores, fp32-grade accuracy
// via 3-product hi/lo splits.
// ---------------------------------------------------------------------------

#define KB   2
#define KL   2048
#define KD   2048
#define KH   16
#define KDH  128
#define KDFF 8192
#define KM   (KB * KL)   // 4096 rows

// ----------------------------- PTX helpers --------------------------------
__device__ __forceinline__ uint32_t smem_u32(const void* p) {
    uint32_t a;
    asm("{ .reg .u64 t; cvta.to.shared.u64 t, %1; cvt.u32.u64 %0, t; }"
        : "=r"(a) : "l"(p));
    return a;
}

// Swizzles: XOR 16B-chunk bits with row bits for conflict-free ldmatrix
#define SWZ64(off)  ((off) ^ (((off) >> 3) & 0x30))   // 64B rows
#define SWZ128(off) ((off) ^ (((off) >> 3) & 0x70))   // 128B rows
#define SWZ256(off) ((off) ^ (((off) >> 4) & 0x70))   // 256B rows

#define CP_ASYNC16(smem, gptr) \
    asm volatile("cp.async.cg.shared.global [%0], [%1], 16;" \
        :: "r"((uint32_t)(smem)), "l"(gptr) : "memory")
#define CP_COMMIT() asm volatile("cp.async.commit_group;" ::: "memory")
#define CP_WAIT2()  asm volatile("cp.async.wait_group 2;" ::: "memory")

#define LDSM_X4(r, addr) \
    asm volatile("ldmatrix.sync.aligned.m8n8.x4.shared.b16 {%0,%1,%2,%3}, [%4];" \
        : "=r"((r)[0]), "=r"((r)[1]), "=r"((r)[2]), "=r"((r)[3]) \
        : "r"((uint32_t)(addr)))

__device__ __forceinline__ void mma_bf16(float* c, const uint32_t* a,
                                         uint32_t b0, uint32_t b1) {
    asm volatile(
        "mma.sync.aligned.m16n8k16.row.col.f32.bf16.bf16.f32 "
        "{%0,%1,%2,%3}, {%4,%5,%6,%7}, {%8,%9}, {%0,%1,%2,%3};"
        : "+f"(c[0]), "+f"(c[1]), "+f"(c[2]), "+f"(c[3])
        : "r"(a[0]), "r"(a[1]), "r"(a[2]), "r"(a[3]), "r"(b0), "r"(b1));
}

__device__ __forceinline__ void split2(float v, __nv_bfloat16& h, __nv_bfloat16& l) {
    h = __float2bfloat16(v);
    l = __float2bfloat16(v - __bfloat162float(h));
}
__device__ __forceinline__ uint32_t pack_bf16(float a, float b) {
    __nv_bfloat162 t = __floats2bfloat162_rn(a, b);   // .x = a (low), .y = b
    return *(uint32_t*)&t;
}

// ------------------------------- scratch ----------------------------------
__device__ __nv_bfloat16 g_wq_h[(size_t)KD * KD];
__device__ __nv_bfloat16 g_wq_l[(size_t)KD * KD];
__device__ __nv_bfloat16 g_wk_h[(size_t)KD * KD];
__device__ __nv_bfloat16 g_wk_l[(size_t)KD * KD];
__device__ __nv_bfloat16 g_wv_h[(size_t)KD * KD];
__device__ __nv_bfloat16 g_wv_l[(size_t)KD * KD];
__device__ __nv_bfloat16 g_wo_h[(size_t)KD * KD];
__device__ __nv_bfloat16 g_wo_l[(size_t)KD * KD];
__device__ __nv_bfloat16 g_wu_h[(size_t)KDFF * KD];
__device__ __nv_bfloat16 g_wu_l[(size_t)KDFF * KD];
__device__ __nv_bfloat16 g_wd_h[(size_t)KD * KDFF];
__device__ __nv_bfloat16 g_wd_l[(size_t)KD * KDFF];
__device__ __nv_bfloat16 g_h_h[(size_t)KM * KD];
__device__ __nv_bfloat16 g_h_l[(size_t)KM * KD];
__device__ __nv_bfloat16 g_q_h[(size_t)KM * KD];
__device__ __nv_bfloat16 g_q_l[(size_t)KM * KD];
__device__ __nv_bfloat16 g_k_h[(size_t)KM * KD];
__device__ __nv_bfloat16 g_k_l[(size_t)KM * KD];
__device__ __nv_bfloat16 g_v_h[(size_t)KM * KD];
__device__ __nv_bfloat16 g_v_l[(size_t)KM * KD];
__device__ __nv_bfloat16 g_o_h[(size_t)KM * KD];
__device__ __nv_bfloat16 g_o_l[(size_t)KM * KD];
__device__ __nv_bfloat16 g_u_h[(size_t)KM * KDFF];
__device__ __nv_bfloat16 g_u_l[(size_t)KM * KDFF];

// ---------------------------------------------------------------------------
// weight split: fp32 -> bf16 hi + bf16 lo
// ---------------------------------------------------------------------------
__global__ __launch_bounds__(256) void split_kernel(
    const float* __restrict__ src, __nv_bfloat16* __restrict__ hi,
    __nv_bfloat16* __restrict__ lo, int n4)
{
    int i = blockIdx.x * 256 + threadIdx.x;
    if (i >= n4) return;
    float4 v = ((const float4*)src)[i];
    __nv_bfloat16 h[4], l[4];
    split2(v.x, h[0], l[0]); split2(v.y, h[1], l[1]);
    split2(v.z, h[2], l[2]); split2(v.w, h[3], l[3]);
    ((uint2*)hi)[i] = *(uint2*)h;
    ((uint2*)lo)[i] = *(uint2*)l;
}

// ---------------------------------------------------------------------------
// RMSNorm with fused hi/lo split output
// ---------------------------------------------------------------------------
__global__ __launch_bounds__(256) void rmsnorm_split_kernel(
    const float* __restrict__ x, const float* __restrict__ w,
    __nv_bfloat16* __restrict__ yh, __nv_bfloat16* __restrict__ yl)
{
    int row = blockIdx.x;
    const float* xr = x + (size_t)row * KD;
    float s = 0.f;
    #pragma unroll
    for (int i = threadIdx.x; i < KD; i += 256) { float v = xr[i]; s += v * v; }
    __shared__ float red[256];
    red[threadIdx.x] = s;
    __syncthreads();
    #pragma unroll
    for (int st = 128; st > 0; st >>= 1) {
        if (threadIdx.x < st) red[threadIdx.x] += red[threadIdx.x + st];
        __syncthreads();
    }
    float inv = rsqrtf(red[0] * (1.0f / KD) + 1e-8f);
    #pragma unroll
    for (int i = threadIdx.x; i < KD; i += 256) {
        float v = xr[i] * inv * w[i];
        __nv_bfloat16 h, l;
        split2(v, h, l);
        yh[(size_t)row * KD + i] = h;
        yl[(size_t)row * KD + i] = l;
    }
}

// ---------------------------------------------------------------------------
// HMMA split-bf16 GEMM:  C[M,N] = A[M,K] @ Bw[N,K]^T
// EPI: 0 fp32 C, 1 GELU->hi/lo bf16, 2 C = R + acc, 3 hi/lo bf16 (no GELU)
// ---------------------------------------------------------------------------
#define TM 128
#define TN 256
#define TKC 32
#define ASPLIT 8192u
#define BSPLIT 16384u
#define STAGE  (2u*ASPLIT + 2u*BSPLIT)
#define NSTAGE 3
#define GEMM_SMEM (NSTAGE * STAGE)

template<int EPI>
__global__ __launch_bounds__(256, 1) void gemm_mma_kernel(
    const __nv_bfloat16* __restrict__ Ah, const __nv_bfloat16* __restrict__ Al,
    const __nv_bfloat16* __restrict__ Bh, const __nv_bfloat16* __restrict__ Bl,
    float* __restrict__ C, const float* __restrict__ R,
    __nv_bfloat16* __restrict__ Chi, __nv_bfloat16* __restrict__ Clo,
    int N, int K)
{
    extern __shared__ char smem[];
    const uint32_t sb = smem_u32(smem);
    const int tid  = threadIdx.x;
    const int wid  = tid >> 5;
    const int lane = tid & 31;
    const int wm   = wid & 1;
    const int wn   = wid >> 1;
    const int bm   = blockIdx.y * TM;
    const int bn   = blockIdx.x * TN;

    const int NC = K / TKC;

    const int mat  = lane >> 3;
    const int rin  = lane & 7;
    const int rowA = (mat & 1) * 8 + rin;
    const int kA   = mat >> 1;
    const int rowB = (mat >> 1) * 8 + rin;
    const int kB   = mat & 1;

    float acc[4][8][4];
    #pragma unroll
    for (int i = 0; i < 4; i++)
        #pragma unroll
        for (int j = 0; j < 8; j++)
            #pragma unroll
            for (int t = 0; t < 4; t++) acc[i][j][t] = 0.f;

    auto load_stage = [&](int c, int s) {
        const int kc = c * TKC;
        const uint32_t base = sb + (uint32_t)s * STAGE;
        #pragma unroll
        for (int i = 0; i < 2; i++) {
            int chunk = i * 256 + tid;
            int r = chunk >> 2, cc = chunk & 3;
            uint32_t so = SWZ64((uint32_t)(r * 64 + cc * 16));
            size_t go = (size_t)(bm + r) * K + kc + cc * 8;
            CP_ASYNC16(base + so,           Ah + go);
            CP_ASYNC16(base + ASPLIT + so,  Al + go);
        }
        #pragma unroll
        for (int i = 0; i < 4; i++) {
            int chunk = i * 256 + tid;
            int r = chunk >> 2, cc = chunk & 3;
            uint32_t so = SWZ64((uint32_t)(r * 64 + cc * 16));
            size_t go = (size_t)(bn + r) * K + kc + cc * 8;
            CP_ASYNC16(base + 2u*ASPLIT + so,          Bh + go);
            CP_ASYNC16(base + 2u*ASPLIT + BSPLIT + so, Bl + go);
        }
        CP_COMMIT();
    };

    load_stage(0, 0);
    if (NC > 1) load_stage(1, 1); else CP_COMMIT();

    for (int c = 0; c < NC; c++) {
        const int s = c % NSTAGE;
        if (c + 2 < NC) load_stage(c + 2, (c + 2) % NSTAGE);
        else            CP_COMMIT();
        CP_WAIT2();
        __syncthreads();

        const uint32_t sAh = sb + (uint32_t)s * STAGE;
        const uint32_t sAl = sAh + ASPLIT;
        const uint32_t sBh = sAl + ASPLIT;
        const uint32_t sBl = sBh + BSPLIT;

        #pragma unroll
        for (int h = 0; h < 2; h++) {
            uint32_t afh[4][4], afl[4][4], bfh[4][4], bfl[4][4];
            #pragma unroll
            for (int mi = 0; mi < 4; mi++) {
                int m = wm * 64 + mi * 16 + rowA;
                uint32_t off = SWZ64((uint32_t)(m * 64 + (h * 2 + kA) * 16));
                LDSM_X4(afh[mi], sAh + off);
                LDSM_X4(afl[mi], sAl + off);
            }
            #pragma unroll
            for (int nj = 0; nj < 4; nj++) {
                int n = wn * 64 + nj * 16 + rowB;
                uint32_t off = SWZ64((uint32_t)(n * 64 + (h * 2 + kB) * 16));
                LDSM_X4(bfh[nj], sBh + off);
                LDSM_X4(bfl[nj], sBl + off);
            }
            #pragma unroll
            for (int mi = 0; mi < 4; mi++)
                #pragma unroll
                for (int nj = 0; nj < 4; nj++)
                    #pragma unroll
                    for (int hf = 0; hf < 2; hf++) {
                        float* cc = acc[mi][nj * 2 + hf];
                        mma_bf16(cc, afh[mi], bfh[nj][hf*2], bfh[nj][hf*2+1]);
                        mma_bf16(cc, afh[mi], bfl[nj][hf*2], bfl[nj][hf*2+1]);
                        mma_bf16(cc, afl[mi], bfh[nj][hf*2], bfh[nj][hf*2+1]);
                    }
        }
        __syncthreads();
    }

    // ---- epilogue ----
    #pragma unroll
    for (int mi = 0; mi < 4; mi++) {
        const int row0 = bm + wm * 64 + mi * 16 + (lane >> 2);
        #pragma unroll
        for (int f = 0; f < 8; f++) {
            const int n0 = bn + wn * 64 + f * 8 + (lane & 3) * 2;
            float* cc = acc[mi][f];
            #pragma unroll
            for (int hrow = 0; hrow < 2; hrow++) {
                const int row = row0 + hrow * 8;
                float v0 = cc[hrow * 2 + 0];
                float v1 = cc[hrow * 2 + 1];
                const size_t idx = (size_t)row * N + n0;
                if (EPI == 1 || EPI == 3) {
                    if (EPI == 1) {
                        v0 = 0.5f * v0 * (1.0f + erff(v0 * 0.70710678118654752f));
                        v1 = 0.5f * v1 * (1.0f + erff(v1 * 0.70710678118654752f));
                    }
                    __nv_bfloat16 h0, l0, h1, l1;
                    split2(v0, h0, l0); split2(v1, h1, l1);
                    __nv_bfloat162 hp; hp.x = h0; hp.y = h1;
                    __nv_bfloat162 lp; lp.x = l0; lp.y = l1;
                    *(__nv_bfloat162*)(Chi + idx) = hp;
                    *(__nv_bfloat162*)(Clo + idx) = lp;
                } else {
                    if (EPI == 2) {
                        float2 rv = *(const float2*)(R + idx);
                        v0 += rv.x; v1 += rv.y;
                    }
                    float2 ov; ov.x = v0; ov.y = v1;
                    *(float2*)(C + idx) = ov;
                }
            }
        }
    }
}

// ---------------------------------------------------------------------------
// Tensor-core causal flash attention (FA2 layout), hi/lo split math.
// Q/K/V given as hi/lo bf16 [B,L,H*DH]. O written as hi/lo bf16.
// CTA: 128 threads (4 warps x m16), 64-query x 64-key tiles.
// ---------------------------------------------------------------------------
#define AT_QH 0u
#define AT_QL 16384u
#define AT_KH 32768u
#define AT_KL 49152u
#define AT_VH 65536u      // V^T [dh=128][key=64] 128B rows
#define AT_VL 81920u
#define ATT_SMEM 98304u

__global__ __launch_bounds__(128, 1) void attn_mma_kernel(
    const __nv_bfloat16* __restrict__ Qh, const __nv_bfloat16* __restrict__ Ql,
    const __nv_bfloat16* __restrict__ Kh, const __nv_bfloat16* __restrict__ Kl,
    const __nv_bfloat16* __restrict__ Vh, const __nv_bfloat16* __restrict__ Vl,
    __nv_bfloat16* __restrict__ Oh, __nv_bfloat16* __restrict__ Ol)
{
    extern __shared__ char smem[];
    const uint32_t sb = smem_u32(smem);
    const int tid  = threadIdx.x;
    const int wid  = tid >> 5;
    const int lane = tid & 31;
    const int bh   = blockIdx.y;
    const int b    = bh >> 4;
    const int h    = bh & 15;
    const int q0   = blockIdx.x * 64;

    const int mat  = lane >> 3;
    const int rin  = lane & 7;
    const int rowA = (mat & 1) * 8 + rin;
    const int kA   = mat >> 1;
    const int rowB = (mat >> 1) * 8 + rin;
    const int kB   = mat & 1;

    const size_t hoff = (size_t)h * KDH;

    // ---- load Q tile (hi/lo) into SMEM: 64 rows x 256B, SWZ256 ----
    #pragma unroll
    for (int i = 0; i < 8; i++) {
        int idx = tid + i * 128;              // 0..1023 16B-chunks
        int r = idx >> 4, cc = idx & 15;
        uint32_t so = SWZ256((uint32_t)(r * 256 + cc * 16));
        size_t go = ((size_t)(b * KL + q0 + r)) * KD + hoff + cc * 8;
        *(uint4*)(smem + AT_QH + so) = *(const uint4*)(Qh + go);
        *(uint4*)(smem + AT_QL + so) = *(const uint4*)(Ql + go);
    }

    float ofrag[16][4];
    #pragma unroll
    for (int g = 0; g < 16; g++)
        #pragma unroll
        for (int t = 0; t < 4; t++) ofrag[g][t] = 0.f;

    float mrow0 = -1e30f, mrow1 = -1e30f;
    float lrow0 = 0.f, lrow1 = 0.f;

    const float scale = 0.08838834764831845f;   // 1/sqrt(128)
    const int qt = blockIdx.x;

    for (int kt = 0; kt <= qt; kt++) {
        const int k0 = kt * 64;
        __syncthreads();
        // ---- load K tile (hi/lo): 64 x 256B ----
        #pragma unroll
        for (int i = 0; i < 8; i++) {
            int idx = tid + i * 128;
            int r = idx >> 4, cc = idx & 15;
            uint32_t so = SWZ256((uint32_t)(r * 256 + cc * 16));
            size_t go = ((size_t)(b * KL + k0 + r)) * KD + hoff + cc * 8;
            *(uint4*)(smem + AT_KH + so) = *(const uint4*)(Kh + go);
            *(uint4*)(smem + AT_KL + so) = *(const uint4*)(Kl + go);
        }
        // ---- load + transpose V tile -> V^T [dh][key], 128B rows ----
        #pragma unroll
        for (int i = 0; i < 16; i++) {
            int idx = tid + i * 128;          // 0..2047 uint2-chunks (4 bf16)
            int key = idx >> 5, d0 = (idx & 31) * 4;
            size_t go = ((size_t)(b * KL + k0 + key)) * KD + hoff + d0;
            uint2 vh4 = *(const uint2*)(Vh + go);
            uint2 vl4 = *(const uint2*)(Vl + go);
            const __nv_bfloat16* ph = (const __nv_bfloat16*)&vh4;
            const __nv_bfloat16* pl = (const __nv_bfloat16*)&vl4;
            #pragma unroll
            for (int d = 0; d < 4; d++) {
                uint32_t so = SWZ128((uint32_t)((d0 + d) * 128 + key * 2));
                *(__nv_bfloat16*)(smem + AT_VH + so) = ph[d];
                *(__nv_bfloat16*)(smem + AT_VL + so) = pl[d];
            }
        }
        __syncthreads();

        // ---- S = Q K^T (3-product split), warp tile m16 x n64, k128 ----
        float sf[8][4];
        #pragma unroll
        for (int f = 0; f < 8; f++)
            #pragma unroll
            for (int t = 0; t < 4; t++) sf[f][t] = 0.f;

        #pragma unroll
        for (int ks = 0; ks < 8; ks++) {
            uint32_t qh[4], ql[4], kh[4][4], kl[4][4];
            {
                uint32_t off = SWZ256((uint32_t)((wid * 16 + rowA) * 256 + ks * 32 + kA * 16));
                LDSM_X4(qh, sb + AT_QH + off);
                LDSM_X4(ql, sb + AT_QL + off);
            }
            #pragma unroll
            for (int nj = 0; nj < 4; nj++) {
                uint32_t off = SWZ256((uint32_t)((nj * 16 + rowB) * 256 + ks * 32 + kB * 16));
                LDSM_X4(kh[nj], sb + AT_KH + off);
                LDSM_X4(kl[nj], sb + AT_KL + off);
            }
            #pragma unroll
            for (int nj = 0; nj < 4; nj++)
                #pragma unroll
                for (int hf = 0; hf < 2; hf++) {
                    float* cc = sf[nj * 2 + hf];
                    mma_bf16(cc, qh, kh[nj][hf*2], kh[nj][hf*2+1]);
                    mma_bf16(cc, qh, kl[nj][hf*2], kl[nj][hf*2+1]);
                    mma_bf16(cc, ql, kh[nj][hf*2], kh[nj][hf*2+1]);
                }
        }

        // ---- scale + causal mask ----
        const int myrow = q0 + wid * 16 + (lane >> 2);
        #pragma unroll
        for (int f = 0; f < 8; f++) {
            #pragma unroll
            for (int t = 0; t < 4; t++) sf[f][t] *= scale;
            if (kt == qt) {
                int col = k0 + f * 8 + (lane & 3) * 2;
                if (col > myrow)     sf[f][0] = -1e30f;
                if (col + 1 > myrow) sf[f][1] = -1e30f;
                if (col > myrow + 8)     sf[f][2] = -1e30f;
                if (col + 1 > myrow + 8) sf[f][3] = -1e30f;
            }
        }

        // ---- online softmax (FA2): row stats over lane-quad groups ----
        float mx0 = -1e30f, mx1 = -1e30f;
        #pragma unroll
        for (int f = 0; f < 8; f++) {
            mx0 = fmaxf(mx0, fmaxf(sf[f][0], sf[f][1]));
            mx1 = fmaxf(mx1, fmaxf(sf[f][2], sf[f][3]));
        }
        #pragma unroll
        for (int d = 1; d <= 2; d <<= 1) {
            mx0 = fmaxf(mx0, __shfl_xor_sync(0xFFFFFFFFu, mx0, d));
            mx1 = fmaxf(mx1, __shfl_xor_sync(0xFFFFFFFFu, mx1, d));
        }
        float mnew0 = fmaxf(mrow0, mx0);
        float mnew1 = fmaxf(mrow1, mx1);
        float alpha0 = __expf(mrow0 - mnew0);
        float alpha1 = __expf(mrow1 - mnew1);
        mrow0 = mnew0; mrow1 = mnew1;

        float rs0 = 0.f, rs1 = 0.f;
        uint32_t pha[8][2], pla[8][2];
        #pragma unroll
        for (int f = 0; f < 8; f++) {
            float p0 = __expf(sf[f][0] - mnew0);
            float p1 = __expf(sf[f][1] - mnew0);
            float p2 = __expf(sf[f][2] - mnew1);
            float p3 = __expf(sf[f][3] - mnew1);
            rs0 += p0 + p1; rs1 += p2 + p3;
            __nv_bfloat16 h0, l0, h1, l1, h2, l2, h3, l3;
            split2(p0, h0, l0); split2(p1, h1, l1);
            split2(p2, h2, l2); split2(p3, h3, l3);
            pha[f][0] = pack_bf16(__bfloat162float(h0), __bfloat162float(h1));
            pha[f][1] = pack_bf16(__bfloat162float(h2), __bfloat162float(h3));
            pla[f][0] = pack_bf16(__bfloat162float(l0), __bfloat162float(l1));
            pla[f][1] = pack_bf16(__bfloat162float(l2), __bfloat162float(l3));
        }
        #pragma unroll
        for (int d = 1; d <= 2; d <<= 1) {
            rs0 += __shfl_xor_sync(0xFFFFFFFFu, rs0, d);
            rs1 += __shfl_xor_sync(0xFFFFFFFFu, rs1, d);
        }
        lrow0 = lrow0 * alpha0 + rs0;
        lrow1 = lrow1 * alpha1 + rs1;

        #pragma unroll
        for (int g = 0; g < 16; g++) {
            ofrag[g][0] *= alpha0; ofrag[g][1] *= alpha0;
            ofrag[g][2] *= alpha1; ofrag[g][3] *= alpha1;
        }

        // ---- O += P V (3-product split), k = 64 keys ----
        #pragma unroll
        for (int kk = 0; kk < 4; kk++) {
            uint32_t pa[4] = {pha[2*kk][0], pha[2*kk][1], pha[2*kk+1][0], pha[2*kk+1][1]};
            uint32_t pb[4] = {pla[2*kk][0], pla[2*kk][1], pla[2*kk+1][0], pla[2*kk+1][1]};
            #pragma unroll
            for (int g = 0; g < 8; g++) {
                uint32_t vh[4], vl[4];
                uint32_t off = SWZ128((uint32_t)((g * 16 + rowB) * 128 + kk * 32 + kB * 16));
                LDSM_X4(vh, sb + AT_VH + off);
                LDSM_X4(vl, sb + AT_VL + off);
                #pragma unroll
                for (int hf = 0; hf < 2; hf++) {
                    float* cc = ofrag[g * 2 + hf];
                    mma_bf16(cc, pa, vh[hf*2], vh[hf*2+1]);
                    mma_bf16(cc, pa, vl[hf*2], vl[hf*2+1]);
                    mma_bf16(cc, pb, vh[hf*2], vh[hf*2+1]);
                }
            }
        }
    }

    // ---- finalize: O / l, write hi/lo ----
    float inv0 = 1.0f / lrow0;
    float inv1 = 1.0f / lrow1;
    const int r0 = q0 + wid * 16 + (lane >> 2);
    #pragma unroll
    for (int g = 0; g < 16; g++) {
        int col = h * KDH + g * 8 + (lane & 3) * 2;
        float v0 = ofrag[g][0] * inv0, v1 = ofrag[g][1] * inv0;
        float v2 = ofrag[g][2] * inv1, v3 = ofrag[g][3] * inv1;
        __nv_bfloat16 h0,l0,h1,l1,h2,l2,h3,l3;
        split2(v0,h0,l0); split2(v1,h1,l1); split2(v2,h2,l2); split2(v3,h3,l3);
        size_t i0 = (size_t)(b * KL + r0) * KD + col;
        size_t i1 = (size_t)(b * KL + r0 + 8) * KD + col;
        __nv_bfloat162 t;
        t.x = h0; t.y = h1; *(__nv_bfloat162*)(Oh + i0) = t;
        t.x = l0; t.y = l1; *(__nv_bfloat162*)(Ol + i0) = t;
        t.x = h2; t.y = h3; *(__nv_bfloat162*)(Oh + i1) = t;
        t.x = l2; t.y = l3; *(__nv_bfloat162*)(Ol + i1) = t;
    }
}

// ---------------------------------------------------------------------------
// kernel_launch
// ---------------------------------------------------------------------------
extern "C" void kernel_launch(void* const* d_in, const int* in_sizes, int n_in,
                              void* d_out, int out_size)
{
    const float* x    = (const float*)d_in[0];
    const float* ln1  = (const float*)d_in[2];
    const float* wq   = (const float*)d_in[3];
    const float* wk   = (const float*)d_in[4];
    const float* wv   = (const float*)d_in[5];
    const float* wo   = (const float*)d_in[6];
    const float* ln2  = (const float*)d_in[7];
    const float* wup  = (const float*)d_in[8];
    const float* wdn  = (const float*)d_in[9];
    float* out = (float*)d_out;

    __nv_bfloat16 *wq_h,*wq_l,*wk_h,*wk_l,*wv_h,*wv_l,*wo_h,*wo_l;
    __nv_bfloat16 *wu_h,*wu_l,*wd_h,*wd_l,*h_h,*h_l,*o_h,*o_l,*u_h,*u_l;
    __nv_bfloat16 *q_h,*q_l,*k_h,*k_l,*v_h,*v_l;
    cudaGetSymbolAddress((void**)&wq_h, g_wq_h);
    cudaGetSymbolAddress((void**)&wq_l, g_wq_l);
    cudaGetSymbolAddress((void**)&wk_h, g_wk_h);
    cudaGetSymbolAddress((void**)&wk_l, g_wk_l);
    cudaGetSymbolAddress((void**)&wv_h, g_wv_h);
    cudaGetSymbolAddress((void**)&wv_l, g_wv_l);
    cudaGetSymbolAddress((void**)&wo_h, g_wo_h);
    cudaGetSymbolAddress((void**)&wo_l, g_wo_l);
    cudaGetSymbolAddress((void**)&wu_h, g_wu_h);
    cudaGetSymbolAddress((void**)&wu_l, g_wu_l);
    cudaGetSymbolAddress((void**)&wd_h, g_wd_h);
    cudaGetSymbolAddress((void**)&wd_l, g_wd_l);
    cudaGetSymbolAddress((void**)&h_h, g_h_h);
    cudaGetSymbolAddress((void**)&h_l, g_h_l);
    cudaGetSymbolAddress((void**)&o_h, g_o_h);
    cudaGetSymbolAddress((void**)&o_l, g_o_l);
    cudaGetSymbolAddress((void**)&u_h, g_u_h);
    cudaGetSymbolAddress((void**)&u_l, g_u_l);
    cudaGetSymbolAddress((void**)&q_h, g_q_h);
    cudaGetSymbolAddress((void**)&q_l, g_q_l);
    cudaGetSymbolAddress((void**)&k_h, g_k_h);
    cudaGetSymbolAddress((void**)&k_l, g_k_l);
    cudaGetSymbolAddress((void**)&v_h, g_v_h);
    cudaGetSymbolAddress((void**)&v_l, g_v_l);

    cudaFuncSetAttribute(gemm_mma_kernel<0>, cudaFuncAttributeMaxDynamicSharedMemorySize, GEMM_SMEM);
    cudaFuncSetAttribute(gemm_mma_kernel<1>, cudaFuncAttributeMaxDynamicSharedMemorySize, GEMM_SMEM);
    cudaFuncSetAttribute(gemm_mma_kernel<2>, cudaFuncAttributeMaxDynamicSharedMemorySize, GEMM_SMEM);
    cudaFuncSetAttribute(gemm_mma_kernel<3>, cudaFuncAttributeMaxDynamicSharedMemorySize, GEMM_SMEM);
    cudaFuncSetAttribute(attn_mma_kernel, cudaFuncAttributeMaxDynamicSharedMemorySize, ATT_SMEM);

    dim3 blk(256);

    // weight splits
    {
        int n4 = KD * KD / 4;
        int g4 = (n4 + 255) / 256;
        split_kernel<<<g4, blk>>>(wq, wq_h, wq_l, n4);
        split_kernel<<<g4, blk>>>(wk, wk_h, wk_l, n4);
        split_kernel<<<g4, blk>>>(wv, wv_h, wv_l, n4);
        split_kernel<<<g4, blk>>>(wo, wo_h, wo_l, n4);
        int n4f = KDFF * KD / 4;
        int g4f = (n4f + 255) / 256;
        split_kernel<<<g4f, blk>>>(wup, wu_h, wu_l, n4f);
        split_kernel<<<g4f, blk>>>(wdn, wd_h, wd_l, n4f);
    }

    // 1. h = rmsnorm(x, ln1) -> hi/lo
    rmsnorm_split_kernel<<<KM, blk>>>(x, ln1, h_h, h_l);

    // 2. q/k/v = h @ W^T -> hi/lo bf16
    dim3 gqkv(KD / TN, KM / TM);
    gemm_mma_kernel<3><<<gqkv, blk, GEMM_SMEM>>>(h_h, h_l, wq_h, wq_l, nullptr, nullptr, q_h, q_l, KD, KD);
    gemm_mma_kernel<3><<<gqkv, blk, GEMM_SMEM>>>(h_h, h_l, wk_h, wk_l, nullptr, nullptr, k_h, k_l, KD, KD);
    gemm_mma_kernel<3><<<gqkv, blk, GEMM_SMEM>>>(h_h, h_l, wv_h, wv_l, nullptr, nullptr, v_h, v_l, KD, KD);

    // 3. o = causal_attention(q,k,v) -> hi/lo
    dim3 gattn(KL / 64, KB * KH);
    attn_mma_kernel<<<gattn, dim3(128), ATT_SMEM>>>(q_h, q_l, k_h, k_l, v_h, v_l, o_h, o_l);

    // 4. out = x + o @ wo^T
    gemm_mma_kernel<2><<<gqkv, blk, GEMM_SMEM>>>(o_h, o_l, wo_h, wo_l, out, x, nullptr, nullptr, KD, KD);

    // 5. h = rmsnorm(out, ln2) -> hi/lo
    rmsnorm_split_kernel<<<KM, blk>>>(out, ln2, h_h, h_l);

    // 6. u = gelu(h @ wup^T) -> hi/lo
    dim3 gup(KDFF / TN, KM / TM);
    gemm_mma_kernel<1><<<gup, blk, GEMM_SMEM>>>(h_h, h_l, wu_h, wu_l, nullptr, nullptr, u_h, u_l, KDFF, KD);

    // 7. out = out + u @ wdn^T
    gemm_mma_kernel<2><<<gqkv, blk, GEMM_SMEM>>>(u_h, u_l, wd_h, wd_l, out, out, nullptr, nullptr, KD, KDFF);
}

// round 6
// speedup vs baseline: 3.1216x; 1.0461x over previous
#include <cuda_runtime.h>
#include <cuda_bf16.h>
#include <math.h>
#include <stdint.h>

// ---------------------------------------------------------------------------
// TransformerBlock  B=2, L=2048, D=2048, H=16, DH=128, DFF=8192
// Round 5: single-sync 4-stage cp.async GEMM mainloop; launch order arranged
// so ncu (-s 5 -c 1) profiles the Q-projection GEMM.
// ---------------------------------------------------------------------------

#define KB   2
#define KL   2048
#define KD   2048
#define KH   16
#define KDH  128
#define KDFF 8192
#define KM   (KB * KL)   // 4096 rows

// ----------------------------- PTX helpers --------------------------------
__device__ __forceinline__ uint32_t smem_u32(const void* p) {
    uint32_t a;
    asm("{ .reg .u64 t; cvta.to.shared.u64 t, %1; cvt.u32.u64 %0, t; }"
        : "=r"(a) : "l"(p));
    return a;
}

#define SWZ64(off)  ((off) ^ (((off) >> 3) & 0x30))   // 64B rows
#define SWZ128(off) ((off) ^ (((off) >> 3) & 0x70))   // 128B rows
#define SWZ256(off) ((off) ^ (((off) >> 4) & 0x70))   // 256B rows

#define CP_ASYNC16(smem, gptr) \
    asm volatile("cp.async.cg.shared.global [%0], [%1], 16;" \
        :: "r"((uint32_t)(smem)), "l"(gptr) : "memory")
#define CP_COMMIT() asm volatile("cp.async.commit_group;" ::: "memory")
#define CP_WAIT2()  asm volatile("cp.async.wait_group 2;" ::: "memory")

#define LDSM_X4(r, addr) \
    asm volatile("ldmatrix.sync.aligned.m8n8.x4.shared.b16 {%0,%1,%2,%3}, [%4];" \
        : "=r"((r)[0]), "=r"((r)[1]), "=r"((r)[2]), "=r"((r)[3]) \
        : "r"((uint32_t)(addr)))

__device__ __forceinline__ void mma_bf16(float* c, const uint32_t* a,
                                         uint32_t b0, uint32_t b1) {
    asm volatile(
        "mma.sync.aligned.m16n8k16.row.col.f32.bf16.bf16.f32 "
        "{%0,%1,%2,%3}, {%4,%5,%6,%7}, {%8,%9}, {%0,%1,%2,%3};"
        : "+f"(c[0]), "+f"(c[1]), "+f"(c[2]), "+f"(c[3])
        : "r"(a[0]), "r"(a[1]), "r"(a[2]), "r"(a[3]), "r"(b0), "r"(b1));
}

__device__ __forceinline__ void split2(float v, __nv_bfloat16& h, __nv_bfloat16& l) {
    h = __float2bfloat16(v);
    l = __float2bfloat16(v - __bfloat162float(h));
}
__device__ __forceinline__ uint32_t pack_bf16(float a, float b) {
    __nv_bfloat162 t = __floats2bfloat162_rn(a, b);
    return *(uint32_t*)&t;
}

// ------------------------------- scratch ----------------------------------
__device__ __nv_bfloat16 g_wq_h[(size_t)KD * KD];
__device__ __nv_bfloat16 g_wq_l[(size_t)KD * KD];
__device__ __nv_bfloat16 g_wk_h[(size_t)KD * KD];
__device__ __nv_bfloat16 g_wk_l[(size_t)KD * KD];
__device__ __nv_bfloat16 g_wv_h[(size_t)KD * KD];
__device__ __nv_bfloat16 g_wv_l[(size_t)KD * KD];
__device__ __nv_bfloat16 g_wo_h[(size_t)KD * KD];
__device__ __nv_bfloat16 g_wo_l[(size_t)KD * KD];
__device__ __nv_bfloat16 g_wu_h[(size_t)KDFF * KD];
__device__ __nv_bfloat16 g_wu_l[(size_t)KDFF * KD];
__device__ __nv_bfloat16 g_wd_h[(size_t)KD * KDFF];
__device__ __nv_bfloat16 g_wd_l[(size_t)KD * KDFF];
__device__ __nv_bfloat16 g_h_h[(size_t)KM * KD];
__device__ __nv_bfloat16 g_h_l[(size_t)KM * KD];
__device__ __nv_bfloat16 g_q_h[(size_t)KM * KD];
__device__ __nv_bfloat16 g_q_l[(size_t)KM * KD];
__device__ __nv_bfloat16 g_k_h[(size_t)KM * KD];
__device__ __nv_bfloat16 g_k_l[(size_t)KM * KD];
__device__ __nv_bfloat16 g_v_h[(size_t)KM * KD];
__device__ __nv_bfloat16 g_v_l[(size_t)KM * KD];
__device__ __nv_bfloat16 g_o_h[(size_t)KM * KD];
__device__ __nv_bfloat16 g_o_l[(size_t)KM * KD];
__device__ __nv_bfloat16 g_u_h[(size_t)KM * KDFF];
__device__ __nv_bfloat16 g_u_l[(size_t)KM * KDFF];

// ---------------------------------------------------------------------------
// weight split: fp32 -> bf16 hi + bf16 lo
// ---------------------------------------------------------------------------
__global__ __launch_bounds__(256) void split_kernel(
    const float* __restrict__ src, __nv_bfloat16* __restrict__ hi,
    __nv_bfloat16* __restrict__ lo, int n4)
{
    int i = blockIdx.x * 256 + threadIdx.x;
    if (i >= n4) return;
    float4 v = ((const float4*)src)[i];
    __nv_bfloat16 h[4], l[4];
    split2(v.x, h[0], l[0]); split2(v.y, h[1], l[1]);
    split2(v.z, h[2], l[2]); split2(v.w, h[3], l[3]);
    ((uint2*)hi)[i] = *(uint2*)h;
    ((uint2*)lo)[i] = *(uint2*)l;
}

// ---------------------------------------------------------------------------
// RMSNorm with fused hi/lo split output
// ---------------------------------------------------------------------------
__global__ __launch_bounds__(256) void rmsnorm_split_kernel(
    const float* __restrict__ x, const float* __restrict__ w,
    __nv_bfloat16* __restrict__ yh, __nv_bfloat16* __restrict__ yl)
{
    int row = blockIdx.x;
    const float* xr = x + (size_t)row * KD;
    float s = 0.f;
    #pragma unroll
    for (int i = threadIdx.x; i < KD; i += 256) { float v = xr[i]; s += v * v; }
    __shared__ float red[256];
    red[threadIdx.x] = s;
    __syncthreads();
    #pragma unroll
    for (int st = 128; st > 0; st >>= 1) {
        if (threadIdx.x < st) red[threadIdx.x] += red[threadIdx.x + st];
        __syncthreads();
    }
    float inv = rsqrtf(red[0] * (1.0f / KD) + 1e-8f);
    #pragma unroll
    for (int i = threadIdx.x; i < KD; i += 256) {
        float v = xr[i] * inv * w[i];
        __nv_bfloat16 h, l;
        split2(v, h, l);
        yh[(size_t)row * KD + i] = h;
        yl[(size_t)row * KD + i] = l;
    }
}

// ---------------------------------------------------------------------------
// HMMA split-bf16 GEMM:  C[M,N] = A[M,K] @ Bw[N,K]^T
// 4-stage cp.async pipeline, single __syncthreads per K-iteration.
// EPI: 0 fp32 C, 1 GELU->hi/lo bf16, 2 C = R + acc, 3 hi/lo bf16 (no GELU)
// ---------------------------------------------------------------------------
#define TM 128
#define TN 256
#define TKC 32
#define ASPLIT 8192u
#define BSPLIT 16384u
#define STAGE  (2u*ASPLIT + 2u*BSPLIT)   // 49152
#define NSTAGE 4
#define GEMM_SMEM (NSTAGE * STAGE)       // 196608

template<int EPI>
__global__ __launch_bounds__(256, 1) void gemm_mma_kernel(
    const __nv_bfloat16* __restrict__ Ah, const __nv_bfloat16* __restrict__ Al,
    const __nv_bfloat16* __restrict__ Bh, const __nv_bfloat16* __restrict__ Bl,
    float* __restrict__ C, const float* __restrict__ R,
    __nv_bfloat16* __restrict__ Chi, __nv_bfloat16* __restrict__ Clo,
    int N, int K)
{
    extern __shared__ char smem[];
    const uint32_t sb = smem_u32(smem);
    const int tid  = threadIdx.x;
    const int wid  = tid >> 5;
    const int lane = tid & 31;
    const int wm   = wid & 1;
    const int wn   = wid >> 1;
    const int bm   = blockIdx.y * TM;
    const int bn   = blockIdx.x * TN;

    const int NC = K / TKC;

    const int mat  = lane >> 3;
    const int rin  = lane & 7;
    const int rowA = (mat & 1) * 8 + rin;
    const int kA   = mat >> 1;
    const int rowB = (mat >> 1) * 8 + rin;
    const int kB   = mat & 1;

    float acc[4][8][4];
    #pragma unroll
    for (int i = 0; i < 4; i++)
        #pragma unroll
        for (int j = 0; j < 8; j++)
            #pragma unroll
            for (int t = 0; t < 4; t++) acc[i][j][t] = 0.f;

    auto load_stage = [&](int c, int s) {
        const int kc = c * TKC;
        const uint32_t base = sb + (uint32_t)s * STAGE;
        #pragma unroll
        for (int i = 0; i < 2; i++) {
            int chunk = i * 256 + tid;
            int r = chunk >> 2, cc = chunk & 3;
            uint32_t so = SWZ64((uint32_t)(r * 64 + cc * 16));
            size_t go = (size_t)(bm + r) * K + kc + cc * 8;
            CP_ASYNC16(base + so,           Ah + go);
            CP_ASYNC16(base + ASPLIT + so,  Al + go);
        }
        #pragma unroll
        for (int i = 0; i < 4; i++) {
            int chunk = i * 256 + tid;
            int r = chunk >> 2, cc = chunk & 3;
            uint32_t so = SWZ64((uint32_t)(r * 64 + cc * 16));
            size_t go = (size_t)(bn + r) * K + kc + cc * 8;
            CP_ASYNC16(base + 2u*ASPLIT + so,          Bh + go);
            CP_ASYNC16(base + 2u*ASPLIT + BSPLIT + so, Bl + go);
        }
        CP_COMMIT();
    };

    load_stage(0, 0);
    load_stage(1, 1);
    load_stage(2, 2);

    #pragma unroll 1
    for (int c = 0; c < NC; c++) {
        const int s = c & 3;
        CP_WAIT2();            // <=2 pending groups => chunk c resident
        __syncthreads();       // all warps done with compute(c-1)
        if (c + 3 < NC) load_stage(c + 3, (c + 3) & 3);

        const uint32_t sAh = sb + (uint32_t)s * STAGE;
        const uint32_t sAl = sAh + ASPLIT;
        const uint32_t sBh = sAl + ASPLIT;
        const uint32_t sBl = sBh + BSPLIT;

        #pragma unroll
        for (int h = 0; h < 2; h++) {
            uint32_t afh[4][4], afl[4][4], bfh[4][4], bfl[4][4];
            #pragma unroll
            for (int mi = 0; mi < 4; mi++) {
                int m = wm * 64 + mi * 16 + rowA;
                uint32_t off = SWZ64((uint32_t)(m * 64 + (h * 2 + kA) * 16));
                LDSM_X4(afh[mi], sAh + off);
                LDSM_X4(afl[mi], sAl + off);
            }
            #pragma unroll
            for (int nj = 0; nj < 4; nj++) {
                int n = wn * 64 + nj * 16 + rowB;
                uint32_t off = SWZ64((uint32_t)(n * 64 + (h * 2 + kB) * 16));
                LDSM_X4(bfh[nj], sBh + off);
                LDSM_X4(bfl[nj], sBl + off);
            }
            #pragma unroll
            for (int mi = 0; mi < 4; mi++)
                #pragma unroll
                for (int nj = 0; nj < 4; nj++)
                    #pragma unroll
                    for (int hf = 0; hf < 2; hf++) {
                        float* cc = acc[mi][nj * 2 + hf];
                        mma_bf16(cc, afh[mi], bfh[nj][hf*2], bfh[nj][hf*2+1]);
                        mma_bf16(cc, afh[mi], bfl[nj][hf*2], bfl[nj][hf*2+1]);
                        mma_bf16(cc, afl[mi], bfh[nj][hf*2], bfh[nj][hf*2+1]);
                    }
        }
    }

    // ---- epilogue (registers only; no smem reuse => no final sync) ----
    #pragma unroll
    for (int mi = 0; mi < 4; mi++) {
        const int row0 = bm + wm * 64 + mi * 16 + (lane >> 2);
        #pragma unroll
        for (int f = 0; f < 8; f++) {
            const int n0 = bn + wn * 64 + f * 8 + (lane & 3) * 2;
            float* cc = acc[mi][f];
            #pragma unroll
            for (int hrow = 0; hrow < 2; hrow++) {
                const int row = row0 + hrow * 8;
                float v0 = cc[hrow * 2 + 0];
                float v1 = cc[hrow * 2 + 1];
                const size_t idx = (size_t)row * N + n0;
                if (EPI == 1 || EPI == 3) {
                    if (EPI == 1) {
                        v0 = 0.5f * v0 * (1.0f + erff(v0 * 0.70710678118654752f));
                        v1 = 0.5f * v1 * (1.0f + erff(v1 * 0.70710678118654752f));
                    }
                    __nv_bfloat16 h0, l0, h1, l1;
                    split2(v0, h0, l0); split2(v1, h1, l1);
                    __nv_bfloat162 hp; hp.x = h0; hp.y = h1;
                    __nv_bfloat162 lp; lp.x = l0; lp.y = l1;
                    *(__nv_bfloat162*)(Chi + idx) = hp;
                    *(__nv_bfloat162*)(Clo + idx) = lp;
                } else {
                    if (EPI == 2) {
                        float2 rv = *(const float2*)(R + idx);
                        v0 += rv.x; v1 += rv.y;
                    }
                    float2 ov; ov.x = v0; ov.y = v1;
                    *(float2*)(C + idx) = ov;
                }
            }
        }
    }
}

// ---------------------------------------------------------------------------
// Tensor-core causal flash attention (FA2 layout), hi/lo split math.
// ---------------------------------------------------------------------------
#define AT_QH 0u
#define AT_QL 16384u
#define AT_KH 32768u
#define AT_KL 49152u
#define AT_VH 65536u
#define AT_VL 81920u
#define ATT_SMEM 98304u

__global__ __launch_bounds__(128, 1) void attn_mma_kernel(
    const __nv_bfloat16* __restrict__ Qh, const __nv_bfloat16* __restrict__ Ql,
    const __nv_bfloat16* __restrict__ Kh, const __nv_bfloat16* __restrict__ Kl,
    const __nv_bfloat16* __restrict__ Vh, const __nv_bfloat16* __restrict__ Vl,
    __nv_bfloat16* __restrict__ Oh, __nv_bfloat16* __restrict__ Ol)
{
    extern __shared__ char smem[];
    const uint32_t sb = smem_u32(smem);
    const int tid  = threadIdx.x;
    const int wid  = tid >> 5;
    const int lane = tid & 31;
    const int bh   = blockIdx.y;
    const int b    = bh >> 4;
    const int h    = bh & 15;
    const int q0   = blockIdx.x * 64;

    const int mat  = lane >> 3;
    const int rin  = lane & 7;
    const int rowA = (mat & 1) * 8 + rin;
    const int kA   = mat >> 1;
    const int rowB = (mat >> 1) * 8 + rin;
    const int kB   = mat & 1;

    const size_t hoff = (size_t)h * KDH;

    #pragma unroll
    for (int i = 0; i < 8; i++) {
        int idx = tid + i * 128;
        int r = idx >> 4, cc = idx & 15;
        uint32_t so = SWZ256((uint32_t)(r * 256 + cc * 16));
        size_t go = ((size_t)(b * KL + q0 + r)) * KD + hoff + cc * 8;
        *(uint4*)(smem + AT_QH + so) = *(const uint4*)(Qh + go);
        *(uint4*)(smem + AT_QL + so) = *(const uint4*)(Ql + go);
    }

    float ofrag[16][4];
    #pragma unroll
    for (int g = 0; g < 16; g++)
        #pragma unroll
        for (int t = 0; t < 4; t++) ofrag[g][t] = 0.f;

    float mrow0 = -1e30f, mrow1 = -1e30f;
    float lrow0 = 0.f, lrow1 = 0.f;

    const float scale = 0.08838834764831845f;
    const int qt = blockIdx.x;

    for (int kt = 0; kt <= qt; kt++) {
        const int k0 = kt * 64;
        __syncthreads();
        #pragma unroll
        for (int i = 0; i < 8; i++) {
            int idx = tid + i * 128;
            int r = idx >> 4, cc = idx & 15;
            uint32_t so = SWZ256((uint32_t)(r * 256 + cc * 16));
            size_t go = ((size_t)(b * KL + k0 + r)) * KD + hoff + cc * 8;
            *(uint4*)(smem + AT_KH + so) = *(const uint4*)(Kh + go);
            *(uint4*)(smem + AT_KL + so) = *(const uint4*)(Kl + go);
        }
        #pragma unroll
        for (int i = 0; i < 16; i++) {
            int idx = tid + i * 128;
            int key = idx >> 5, d0 = (idx & 31) * 4;
            size_t go = ((size_t)(b * KL + k0 + key)) * KD + hoff + d0;
            uint2 vh4 = *(const uint2*)(Vh + go);
            uint2 vl4 = *(const uint2*)(Vl + go);
            const __nv_bfloat16* ph = (const __nv_bfloat16*)&vh4;
            const __nv_bfloat16* pl = (const __nv_bfloat16*)&vl4;
            #pragma unroll
            for (int d = 0; d < 4; d++) {
                uint32_t so = SWZ128((uint32_t)((d0 + d) * 128 + key * 2));
                *(__nv_bfloat16*)(smem + AT_VH + so) = ph[d];
                *(__nv_bfloat16*)(smem + AT_VL + so) = pl[d];
            }
        }
        __syncthreads();

        float sf[8][4];
        #pragma unroll
        for (int f = 0; f < 8; f++)
            #pragma unroll
            for (int t = 0; t < 4; t++) sf[f][t] = 0.f;

        #pragma unroll
        for (int ks = 0; ks < 8; ks++) {
            uint32_t qh[4], ql[4], kh[4][4], kl[4][4];
            {
                uint32_t off = SWZ256((uint32_t)((wid * 16 + rowA) * 256 + ks * 32 + kA * 16));
                LDSM_X4(qh, sb + AT_QH + off);
                LDSM_X4(ql, sb + AT_QL + off);
            }
            #pragma unroll
            for (int nj = 0; nj < 4; nj++) {
                uint32_t off = SWZ256((uint32_t)((nj * 16 + rowB) * 256 + ks * 32 + kB * 16));
                LDSM_X4(kh[nj], sb + AT_KH + off);
                LDSM_X4(kl[nj], sb + AT_KL + off);
            }
            #pragma unroll
            for (int nj = 0; nj < 4; nj++)
                #pragma unroll
                for (int hf = 0; hf < 2; hf++) {
                    float* cc = sf[nj * 2 + hf];
                    mma_bf16(cc, qh, kh[nj][hf*2], kh[nj][hf*2+1]);
                    mma_bf16(cc, qh, kl[nj][hf*2], kl[nj][hf*2+1]);
                    mma_bf16(cc, ql, kh[nj][hf*2], kh[nj][hf*2+1]);
                }
        }

        const int myrow = q0 + wid * 16 + (lane >> 2);
        #pragma unroll
        for (int f = 0; f < 8; f++) {
            #pragma unroll
            for (int t = 0; t < 4; t++) sf[f][t] *= scale;
            if (kt == qt) {
                int col = k0 + f * 8 + (lane & 3) * 2;
                if (col > myrow)     sf[f][0] = -1e30f;
                if (col + 1 > myrow) sf[f][1] = -1e30f;
                if (col > myrow + 8)     sf[f][2] = -1e30f;
                if (col + 1 > myrow + 8) sf[f][3] = -1e30f;
            }
        }

        float mx0 = -1e30f, mx1 = -1e30f;
        #pragma unroll
        for (int f = 0; f < 8; f++) {
            mx0 = fmaxf(mx0, fmaxf(sf[f][0], sf[f][1]));
            mx1 = fmaxf(mx1, fmaxf(sf[f][2], sf[f][3]));
        }
        #pragma unroll
        for (int d = 1; d <= 2; d <<= 1) {
            mx0 = fmaxf(mx0, __shfl_xor_sync(0xFFFFFFFFu, mx0, d));
            mx1 = fmaxf(mx1, __shfl_xor_sync(0xFFFFFFFFu, mx1, d));
        }
        float mnew0 = fmaxf(mrow0, mx0);
        float mnew1 = fmaxf(mrow1, mx1);
        float alpha0 = __expf(mrow0 - mnew0);
        float alpha1 = __expf(mrow1 - mnew1);
        mrow0 = mnew0; mrow1 = mnew1;

        float rs0 = 0.f, rs1 = 0.f;
        uint32_t pha[8][2], pla[8][2];
        #pragma unroll
        for (int f = 0; f < 8; f++) {
            float p0 = __expf(sf[f][0] - mnew0);
            float p1 = __expf(sf[f][1] - mnew0);
            float p2 = __expf(sf[f][2] - mnew1);
            float p3 = __expf(sf[f][3] - mnew1);
            rs0 += p0 + p1; rs1 += p2 + p3;
            __nv_bfloat16 h0, l0, h1, l1, h2, l2, h3, l3;
            split2(p0, h0, l0); split2(p1, h1, l1);
            split2(p2, h2, l2); split2(p3, h3, l3);
            pha[f][0] = pack_bf16(__bfloat162float(h0), __bfloat162float(h1));
            pha[f][1] = pack_bf16(__bfloat162float(h2), __bfloat162float(h3));
            pla[f][0] = pack_bf16(__bfloat162float(l0), __bfloat162float(l1));
            pla[f][1] = pack_bf16(__bfloat162float(l2), __bfloat162float(l3));
        }
        #pragma unroll
        for (int d = 1; d <= 2; d <<= 1) {
            rs0 += __shfl_xor_sync(0xFFFFFFFFu, rs0, d);
            rs1 += __shfl_xor_sync(0xFFFFFFFFu, rs1, d);
        }
        lrow0 = lrow0 * alpha0 + rs0;
        lrow1 = lrow1 * alpha1 + rs1;

        #pragma unroll
        for (int g = 0; g < 16; g++) {
            ofrag[g][0] *= alpha0; ofrag[g][1] *= alpha0;
            ofrag[g][2] *= alpha1; ofrag[g][3] *= alpha1;
        }

        #pragma unroll
        for (int kk = 0; kk < 4; kk++) {
            uint32_t pa[4] = {pha[2*kk][0], pha[2*kk][1], pha[2*kk+1][0], pha[2*kk+1][1]};
            uint32_t pb[4] = {pla[2*kk][0], pla[2*kk][1], pla[2*kk+1][0], pla[2*kk+1][1]};
            #pragma unroll
            for (int g = 0; g < 8; g++) {
                uint32_t vh[4], vl[4];
                uint32_t off = SWZ128((uint32_t)((g * 16 + rowB) * 128 + kk * 32 + kB * 16));
                LDSM_X4(vh, sb + AT_VH + off);
                LDSM_X4(vl, sb + AT_VL + off);
                #pragma unroll
                for (int hf = 0; hf < 2; hf++) {
                    float* cc = ofrag[g * 2 + hf];
                    mma_bf16(cc, pa, vh[hf*2], vh[hf*2+1]);
                    mma_bf16(cc, pa, vl[hf*2], vl[hf*2+1]);
                    mma_bf16(cc, pb, vh[hf*2], vh[hf*2+1]);
                }
            }
        }
    }

    float inv0 = 1.0f / lrow0;
    float inv1 = 1.0f / lrow1;
    const int r0 = q0 + wid * 16 + (lane >> 2);
    #pragma unroll
    for (int g = 0; g < 16; g++) {
        int col = h * KDH + g * 8 + (lane & 3) * 2;
        float v0 = ofrag[g][0] * inv0, v1 = ofrag[g][1] * inv0;
        float v2 = ofrag[g][2] * inv1, v3 = ofrag[g][3] * inv1;
        __nv_bfloat16 h0,l0,h1,l1,h2,l2,h3,l3;
        split2(v0,h0,l0); split2(v1,h1,l1); split2(v2,h2,l2); split2(v3,h3,l3);
        size_t i0 = (size_t)(b * KL + r0) * KD + col;
        size_t i1 = (size_t)(b * KL + r0 + 8) * KD + col;
        __nv_bfloat162 t;
        t.x = h0; t.y = h1; *(__nv_bfloat162*)(Oh + i0) = t;
        t.x = l0; t.y = l1; *(__nv_bfloat162*)(Ol + i0) = t;
        t.x = h2; t.y = h3; *(__nv_bfloat162*)(Oh + i1) = t;
        t.x = l2; t.y = l3; *(__nv_bfloat162*)(Ol + i1) = t;
    }
}

// ---------------------------------------------------------------------------
// kernel_launch — launch order arranged so launch #6 (0-based #5) is the
// Q-projection GEMM, which ncu (-s 5 -c 1) will profile.
// ---------------------------------------------------------------------------
extern "C" void kernel_launch(void* const* d_in, const int* in_sizes, int n_in,
                              void* d_out, int out_size)
{
    const float* x    = (const float*)d_in[0];
    const float* ln1  = (const float*)d_in[2];
    const float* wq   = (const float*)d_in[3];
    const float* wk   = (const float*)d_in[4];
    const float* wv   = (const float*)d_in[5];
    const float* wo   = (const float*)d_in[6];
    const float* ln2  = (const float*)d_in[7];
    const float* wup  = (const float*)d_in[8];
    const float* wdn  = (const float*)d_in[9];
    float* out = (float*)d_out;

    __nv_bfloat16 *wq_h,*wq_l,*wk_h,*wk_l,*wv_h,*wv_l,*wo_h,*wo_l;
    __nv_bfloat16 *wu_h,*wu_l,*wd_h,*wd_l,*h_h,*h_l,*o_h,*o_l,*u_h,*u_l;
    __nv_bfloat16 *q_h,*q_l,*k_h,*k_l,*v_h,*v_l;
    cudaGetSymbolAddress((void**)&wq_h, g_wq_h);
    cudaGetSymbolAddress((void**)&wq_l, g_wq_l);
    cudaGetSymbolAddress((void**)&wk_h, g_wk_h);
    cudaGetSymbolAddress((void**)&wk_l, g_wk_l);
    cudaGetSymbolAddress((void**)&wv_h, g_wv_h);
    cudaGetSymbolAddress((void**)&wv_l, g_wv_l);
    cudaGetSymbolAddress((void**)&wo_h, g_wo_h);
    cudaGetSymbolAddress((void**)&wo_l, g_wo_l);
    cudaGetSymbolAddress((void**)&wu_h, g_wu_h);
    cudaGetSymbolAddress((void**)&wu_l, g_wu_l);
    cudaGetSymbolAddress((void**)&wd_h, g_wd_h);
    cudaGetSymbolAddress((void**)&wd_l, g_wd_l);
    cudaGetSymbolAddress((void**)&h_h, g_h_h);
    cudaGetSymbolAddress((void**)&h_l, g_h_l);
    cudaGetSymbolAddress((void**)&o_h, g_o_h);
    cudaGetSymbolAddress((void**)&o_l, g_o_l);
    cudaGetSymbolAddress((void**)&u_h, g_u_h);
    cudaGetSymbolAddress((void**)&u_l, g_u_l);
    cudaGetSymbolAddress((void**)&q_h, g_q_h);
    cudaGetSymbolAddress((void**)&q_l, g_q_l);
    cudaGetSymbolAddress((void**)&k_h, g_k_h);
    cudaGetSymbolAddress((void**)&k_l, g_k_l);
    cudaGetSymbolAddress((void**)&v_h, g_v_h);
    cudaGetSymbolAddress((void**)&v_l, g_v_l);

    cudaFuncSetAttribute(gemm_mma_kernel<0>, cudaFuncAttributeMaxDynamicSharedMemorySize, GEMM_SMEM);
    cudaFuncSetAttribute(gemm_mma_kernel<1>, cudaFuncAttributeMaxDynamicSharedMemorySize, GEMM_SMEM);
    cudaFuncSetAttribute(gemm_mma_kernel<2>, cudaFuncAttributeMaxDynamicSharedMemorySize, GEMM_SMEM);
    cudaFuncSetAttribute(gemm_mma_kernel<3>, cudaFuncAttributeMaxDynamicSharedMemorySize, GEMM_SMEM);
    cudaFuncSetAttribute(attn_mma_kernel, cudaFuncAttributeMaxDynamicSharedMemorySize, ATT_SMEM);

    dim3 blk(256);
    dim3 gqkv(KD / TN, KM / TM);
    dim3 gup(KDFF / TN, KM / TM);

    const int n4  = KD * KD / 4;
    const int g4  = (n4 + 255) / 256;
    const int n4f = KDFF * KD / 4;
    const int g4f = (n4f + 255) / 256;

    // launches 0..4
    rmsnorm_split_kernel<<<KM, blk>>>(x, ln1, h_h, h_l);
    split_kernel<<<g4, blk>>>(wq, wq_h, wq_l, n4);
    split_kernel<<<g4, blk>>>(wk, wk_h, wk_l, n4);
    split_kernel<<<g4, blk>>>(wv, wv_h, wv_l, n4);
    split_kernel<<<g4, blk>>>(wo, wo_h, wo_l, n4);

    // launch 5 — profiled by ncu (-s 5 -c 1)
    gemm_mma_kernel<3><<<gqkv, blk, GEMM_SMEM>>>(h_h, h_l, wq_h, wq_l, nullptr, nullptr, q_h, q_l, KD, KD);
    gemm_mma_kernel<3><<<gqkv, blk, GEMM_SMEM>>>(h_h, h_l, wk_h, wk_l, nullptr, nullptr, k_h, k_l, KD, KD);
    gemm_mma_kernel<3><<<gqkv, blk, GEMM_SMEM>>>(h_h, h_l, wv_h, wv_l, nullptr, nullptr, v_h, v_l, KD, KD);

    // FFN weight splits (needed later; placed here, still sequential stream)
    split_kernel<<<g4f, blk>>>(wup, wu_h, wu_l, n4f);
    split_kernel<<<g4f, blk>>>(wdn, wd_h, wd_l, n4f);

    // attention
    dim3 gattn(KL / 64, KB * KH);
    attn_mma_kernel<<<gattn, dim3(128), ATT_SMEM>>>(q_h, q_l, k_h, k_l, v_h, v_l, o_h, o_l);

    // out = x + o @ wo^T
    gemm_mma_kernel<2><<<gqkv, blk, GEMM_SMEM>>>(o_h, o_l, wo_h, wo_l, out, x, nullptr, nullptr, KD, KD);

    // h = rmsnorm(out, ln2)
    rmsnorm_split_kernel<<<KM, blk>>>(out, ln2, h_h, h_l);

    // u = gelu(h @ wup^T)
    gemm_mma_kernel<1><<<gup, blk, GEMM_SMEM>>>(h_h, h_l, wu_h, wu_l, nullptr, nullptr, u_h, u_l, KDFF, KD);

    // out = out + u @ wdn^T
    gemm_mma_kernel<2><<<gqkv, blk, GEMM_SMEM>>>(u_h, u_l, wd_h, wd_l, out, out, nullptr, nullptr, KD, KDFF);
}